// round 5
// baseline (speedup 1.0000x reference)
#include <cuda_runtime.h>
#include <cuda_bf16.h>
#include <cstdint>
#include <math.h>

#define D_HID 2048
#define INTER 1408
#define NGU   2816
#define NEXP  8
#define TMAX  4096
#define TPAIR 8192
#define RMAX  9216

// ---------------- device scratch ----------------
__device__ int   g_count[NEXP];
__device__ int   g_top_e[TPAIR];
__device__ int   g_pos[TPAIR];
__device__ int   g_p2s[TPAIR];
__device__ float g_wt[TPAIR];
__device__ __align__(256) __nv_bfloat16 g_xg_hi [(size_t)RMAX * D_HID];
__device__ __align__(256) __nv_bfloat16 g_xg_lo [(size_t)RMAX * D_HID];
__device__ __align__(256) __nv_bfloat16 g_gup_hi[(size_t)NEXP * NGU * D_HID];
__device__ __align__(256) __nv_bfloat16 g_gup_lo[(size_t)NEXP * NGU * D_HID];
__device__ __align__(256) __nv_bfloat16 g_dwn_hi[(size_t)NEXP * D_HID * INTER];
__device__ __align__(256) __nv_bfloat16 g_dwn_lo[(size_t)NEXP * D_HID * INTER];
__device__ __align__(256) __nv_bfloat16 g_h_hi  [(size_t)RMAX * INTER];
__device__ __align__(256) __nv_bfloat16 g_h_lo  [(size_t)RMAX * INTER];
__device__ __align__(256) float         g_ct    [(size_t)RMAX * D_HID];

// ---------------- helpers ----------------
__device__ __forceinline__ uint32_t smem_u32(const void* p) {
    uint32_t a;
    asm("{ .reg .u64 t; cvta.to.shared.u64 t, %1; cvt.u32.u64 %0, t; }" : "=r"(a) : "l"(p));
    return a;
}
__device__ __forceinline__ void cp16z(uint32_t dst, const void* src, uint32_t sz) {
    asm volatile("cp.async.cg.shared.global [%0], [%1], 16, %2;"
                 :: "r"(dst), "l"(src), "r"(sz));
}
__device__ __forceinline__ void ldsm4(uint32_t* r, uint32_t addr) {
    asm volatile("ldmatrix.sync.aligned.m8n8.x4.shared.b16 {%0,%1,%2,%3}, [%4];"
                 : "=r"(r[0]), "=r"(r[1]), "=r"(r[2]), "=r"(r[3]) : "r"(addr));
}
__device__ __forceinline__ void mma_bf16(float* d, const uint32_t* a, const uint32_t* b) {
    asm volatile("mma.sync.aligned.m16n8k16.row.col.f32.bf16.bf16.f32 "
                 "{%0,%1,%2,%3}, {%4,%5,%6,%7}, {%8,%9}, {%0,%1,%2,%3};"
                 : "+f"(d[0]), "+f"(d[1]), "+f"(d[2]), "+f"(d[3])
                 : "r"(a[0]), "r"(a[1]), "r"(a[2]), "r"(a[3]), "r"(b[0]), "r"(b[1]));
}
__device__ __forceinline__ void f2bf2(float x, __nv_bfloat16& hi, __nv_bfloat16& lo) {
    hi = __float2bfloat16(x);
    lo = __float2bfloat16(x - __bfloat162float(hi));
}
__device__ __forceinline__ int expert_base(int e) {
    int o = 0;
#pragma unroll
    for (int k = 0; k < NEXP; k++)
        if (k < e) o += (g_count[k] + 127) & ~127;
    return o;
}

// ---------------- init ----------------
__global__ void zero_counts_kernel() {
    if (threadIdx.x < NEXP) g_count[threadIdx.x] = 0;
}

// ---------------- router ----------------
__global__ void router_kernel(const float* __restrict__ x,
                              const float* __restrict__ rw) {
    int t = blockIdx.x;
    const float* xr = x + (size_t)t * D_HID;
    float p[NEXP];
#pragma unroll
    for (int e = 0; e < NEXP; e++) p[e] = 0.f;
    for (int d = threadIdx.x; d < D_HID; d += blockDim.x) {
        float xv = xr[d];
#pragma unroll
        for (int e = 0; e < NEXP; e++)
            p[e] = fmaf(xv, rw[e * D_HID + d], p[e]);
    }
#pragma unroll
    for (int off = 16; off > 0; off >>= 1)
#pragma unroll
        for (int e = 0; e < NEXP; e++)
            p[e] += __shfl_down_sync(0xffffffffu, p[e], off);
    __shared__ float s[8][NEXP];
    int warp = threadIdx.x >> 5;
    if ((threadIdx.x & 31) == 0)
#pragma unroll
        for (int e = 0; e < NEXP; e++) s[warp][e] = p[e];
    __syncthreads();
    if (threadIdx.x == 0) {
        float l[NEXP];
#pragma unroll
        for (int e = 0; e < NEXP; e++) {
            float a = 0.f;
#pragma unroll
            for (int w = 0; w < 8; w++) a += s[w][e];
            l[e] = a;
        }
        int i0 = 0;
#pragma unroll
        for (int e = 1; e < NEXP; e++) if (l[e] > l[i0]) i0 = e;
        int i1 = (i0 == 0) ? 1 : 0;
#pragma unroll
        for (int e = 0; e < NEXP; e++)
            if (e != i0 && l[e] > l[i1]) i1 = e;
        float e1  = expf(l[i1] - l[i0]);
        float inv = 1.f / (1.f + e1);
        g_wt[2*t]   = inv;
        g_wt[2*t+1] = e1 * inv;
        int p0 = atomicAdd(&g_count[i0], 1);
        g_top_e[2*t] = i0; g_pos[2*t] = p0;
        int p1 = atomicAdd(&g_count[i1], 1);
        g_top_e[2*t+1] = i1; g_pos[2*t+1] = p1;
    }
}

// ---------------- prep: gather-x + weight conversions ----------------
__global__ void prep_kernel(const float* __restrict__ x,
                            const float* __restrict__ gup,
                            const float* __restrict__ dwn) {
    int b = blockIdx.x;
    if (b < TPAIR) {
        int p = b;
        int t = p >> 1;
        int s = expert_base(g_top_e[p]) + g_pos[p];
        if (threadIdx.x == 0) g_p2s[p] = s;
        const float4* src = (const float4*)(x + (size_t)t * D_HID);
        __nv_bfloat162* dh = (__nv_bfloat162*)(g_xg_hi + (size_t)s * D_HID);
        __nv_bfloat162* dl = (__nv_bfloat162*)(g_xg_lo + (size_t)s * D_HID);
        for (int i = threadIdx.x; i < D_HID/4; i += blockDim.x) {
            float4 v = src[i];
            __nv_bfloat16 h0,l0,h1,l1,h2,l2,h3,l3;
            f2bf2(v.x,h0,l0); f2bf2(v.y,h1,l1); f2bf2(v.z,h2,l2); f2bf2(v.w,h3,l3);
            __nv_bfloat162 a; a.x = h0; a.y = h1;
            __nv_bfloat162 c; c.x = h2; c.y = h3;
            dh[2*i] = a; dh[2*i+1] = c;
            a.x = l0; a.y = l1; c.x = l2; c.y = l3;
            dl[2*i] = a; dl[2*i+1] = c;
        }
    } else if (b < TPAIR + NEXP * NGU) {
        int row = b - TPAIR;
        int e = row / NGU;
        int n = row % NGU;
        int blk = n >> 6, r = n & 63;
        int src_n = (r < 32) ? (blk*32 + r) : (INTER + blk*32 + (r - 32));
        const float4* src = (const float4*)(gup + ((size_t)e * NGU + src_n) * D_HID);
        __nv_bfloat162* dh = (__nv_bfloat162*)(g_gup_hi + (size_t)row * D_HID);
        __nv_bfloat162* dl = (__nv_bfloat162*)(g_gup_lo + (size_t)row * D_HID);
        for (int i = threadIdx.x; i < D_HID/4; i += blockDim.x) {
            float4 v = src[i];
            __nv_bfloat16 h0,l0,h1,l1,h2,l2,h3,l3;
            f2bf2(v.x,h0,l0); f2bf2(v.y,h1,l1); f2bf2(v.z,h2,l2); f2bf2(v.w,h3,l3);
            __nv_bfloat162 a; a.x = h0; a.y = h1;
            __nv_bfloat162 c; c.x = h2; c.y = h3;
            dh[2*i] = a; dh[2*i+1] = c;
            a.x = l0; a.y = l1; c.x = l2; c.y = l3;
            dl[2*i] = a; dl[2*i+1] = c;
        }
    } else {
        int row = b - TPAIR - NEXP * NGU;
        const float4* src = (const float4*)(dwn + (size_t)row * INTER);
        __nv_bfloat162* dh = (__nv_bfloat162*)(g_dwn_hi + (size_t)row * INTER);
        __nv_bfloat162* dl = (__nv_bfloat162*)(g_dwn_lo + (size_t)row * INTER);
        for (int i = threadIdx.x; i < INTER/4; i += blockDim.x) {
            float4 v = src[i];
            __nv_bfloat16 h0,l0,h1,l1,h2,l2,h3,l3;
            f2bf2(v.x,h0,l0); f2bf2(v.y,h1,l1); f2bf2(v.z,h2,l2); f2bf2(v.w,h3,l3);
            __nv_bfloat162 a; a.x = h0; a.y = h1;
            __nv_bfloat162 c; c.x = h2; c.y = h3;
            dh[2*i] = a; dh[2*i+1] = c;
            a.x = l0; a.y = l1; c.x = l2; c.y = l3;
            dl[2*i] = a; dl[2*i+1] = c;
        }
    }
}

// ---------------- HMMA grouped GEMM (bf16x3), CTA 128x256, 512 thr ----------
#define PITCH 80
#define A_TILE (128*PITCH)
#define B_TILE (256*PITCH)
#define AH_OFF 0
#define AL_OFF A_TILE
#define BH_OFF (2*A_TILE)
#define BL_OFF (2*A_TILE + B_TILE)
#define STAGE  (2*A_TILE + 2*B_TILE)
#define NSTG   3
#define GEMM_SMEM (NSTG*STAGE)

template <int PHASE>
__global__ void __launch_bounds__(512, 1)
moe_gemm_kernel() {
    constexpr int Kd  = (PHASE == 0) ? D_HID : INTER;
    constexpr int NCH = Kd / 32;
    constexpr int NROW = (PHASE == 0) ? NGU : D_HID;

    int e   = blockIdx.z;
    int cnt = g_count[e];
    int m0  = blockIdx.x * 128;
    if (m0 >= cnt) return;
    int n0  = blockIdx.y * 256;
    int off_e = expert_base(e);

    const __nv_bfloat16* Ahi = ((PHASE == 0) ? g_xg_hi : g_h_hi) + (size_t)(off_e + m0) * Kd;
    const __nv_bfloat16* Alo = ((PHASE == 0) ? g_xg_lo : g_h_lo) + (size_t)(off_e + m0) * Kd;
    const __nv_bfloat16* Bhi = ((PHASE == 0) ? g_gup_hi : g_dwn_hi) + ((size_t)e * NROW + n0) * Kd;
    const __nv_bfloat16* Blo = ((PHASE == 0) ? g_gup_lo : g_dwn_lo) + ((size_t)e * NROW + n0) * Kd;

    extern __shared__ __align__(128) char smem[];
    uint32_t sb = smem_u32(smem);

    int tid = threadIdx.x;
    int wid = tid >> 5;
    int lid = tid & 31;
    int warp_m = (wid >> 2) * 32;
    int warp_n = (wid & 3) * 64;

    int ra  = tid >> 2, qa = tid & 3;
    int rb1 = (tid + 512) >> 2;
    uint32_t soA  = (uint32_t)(ra  * PITCH + qa * 16);
    uint32_t soB1 = (uint32_t)(rb1 * PITCH + qa * 16);
    const char* pAh  = (const char*)(Ahi + (size_t)ra  * Kd + qa * 8);
    const char* pAl  = (const char*)(Alo + (size_t)ra  * Kd + qa * 8);
    const char* pBh0 = (const char*)(Bhi + (size_t)ra  * Kd + qa * 8);
    const char* pBl0 = (const char*)(Blo + (size_t)ra  * Kd + qa * 8);
    const char* pBh1 = (const char*)(Bhi + (size_t)rb1 * Kd + qa * 8);
    const char* pBl1 = (const char*)(Blo + (size_t)rb1 * Kd + qa * 8);
    uint32_t szA = (m0 + ra < cnt) ? 16u : 0u;

    uint32_t a_off = (uint32_t)((warp_m + (lid & 15)) * PITCH + (lid >> 4) * 16);
    uint32_t b_off = (uint32_t)((warp_n + (lid & 7) + ((lid & 16) >> 1)) * PITCH +
                                ((lid >> 3) & 1) * 16);

    float d[2][8][4];
#pragma unroll
    for (int mi = 0; mi < 2; mi++)
#pragma unroll
        for (int ni = 0; ni < 8; ni++)
#pragma unroll
            for (int k = 0; k < 4; k++) d[mi][ni][k] = 0.f;

    auto load_chunk = [&](int ci, int s) {
        uint32_t st = sb + s * STAGE;
        size_t go = (size_t)ci * 64;
        cp16z(st + AH_OFF + soA,  pAh  + go, szA);
        cp16z(st + AL_OFF + soA,  pAl  + go, szA);
        cp16z(st + BH_OFF + soA,  pBh0 + go, 16u);
        cp16z(st + BL_OFF + soA,  pBl0 + go, 16u);
        cp16z(st + BH_OFF + soB1, pBh1 + go, 16u);
        cp16z(st + BL_OFF + soB1, pBl1 + go, 16u);
    };

    load_chunk(0, 0);
    asm volatile("cp.async.commit_group;" ::: "memory");
    load_chunk(1, 1);
    asm volatile("cp.async.commit_group;" ::: "memory");

    int sidx = 0, lidx = 2;
#pragma unroll 1
    for (int i = 0; i < NCH; i++) {
        asm volatile("cp.async.wait_group 1;" ::: "memory");
        __syncthreads();
        if (i + 2 < NCH) load_chunk(i + 2, lidx);
        asm volatile("cp.async.commit_group;" ::: "memory");

        uint32_t st = sb + sidx * STAGE;
#pragma unroll
        for (int kk = 0; kk < 2; kk++) {
            uint32_t ko = kk * 32;
            uint32_t ah[2][4], al[2][4];
            ldsm4(ah[0], st + AH_OFF + a_off + ko);
            ldsm4(ah[1], st + AH_OFF + a_off + ko + 16 * PITCH);
            ldsm4(al[0], st + AL_OFF + a_off + ko);
            ldsm4(al[1], st + AL_OFF + a_off + ko + 16 * PITCH);
            // process np pairs: {0,1} then {2,3}
#pragma unroll
            for (int pp = 0; pp < 2; pp++) {
                uint32_t bh[2][4], bl[2][4];
                ldsm4(bh[0], st + BH_OFF + b_off + ko + (pp*2 + 0) * 16 * PITCH);
                ldsm4(bh[1], st + BH_OFF + b_off + ko + (pp*2 + 1) * 16 * PITCH);
                ldsm4(bl[0], st + BL_OFF + b_off + ko + (pp*2 + 0) * 16 * PITCH);
                ldsm4(bl[1], st + BL_OFF + b_off + ko + (pp*2 + 1) * 16 * PITCH);
                // product-major: 8 independent accumulator chains per step
#pragma unroll
                for (int mi = 0; mi < 2; mi++)
#pragma unroll
                    for (int q = 0; q < 4; q++)
                        mma_bf16(d[mi][pp*4 + q], ah[mi], &bh[q >> 1][(q & 1) * 2]);
#pragma unroll
                for (int mi = 0; mi < 2; mi++)
#pragma unroll
                    for (int q = 0; q < 4; q++)
                        mma_bf16(d[mi][pp*4 + q], ah[mi], &bl[q >> 1][(q & 1) * 2]);
#pragma unroll
                for (int mi = 0; mi < 2; mi++)
#pragma unroll
                    for (int q = 0; q < 4; q++)
                        mma_bf16(d[mi][pp*4 + q], al[mi], &bh[q >> 1][(q & 1) * 2]);
            }
        }
        sidx = (sidx == NSTG-1) ? 0 : sidx + 1;
        lidx = (lidx == NSTG-1) ? 0 : lidx + 1;
    }

    // ---------------- epilogue ----------------
    if (PHASE == 0) {
        int icb = blockIdx.y * 128 + (warp_n >> 1);
#pragma unroll
        for (int mi = 0; mi < 2; mi++) {
            int rA = warp_m + mi * 16 + (lid >> 2);
            int rB = rA + 8;
            bool vA = (m0 + rA) < cnt;
            bool vB = (m0 + rB) < cnt;
            size_t rowA = (size_t)(off_e + m0 + rA);
            size_t rowB = (size_t)(off_e + m0 + rB);
#pragma unroll
            for (int ni = 0; ni < 4; ni++) {
                int col = icb + ni * 8 + (lid & 3) * 2;
                const float* g = d[mi][ni];
                const float* u = d[mi][ni + 4];
                if (vA) {
                    float h0 = g[0] / (1.f + expf(-g[0])) * u[0];
                    float h1 = g[1] / (1.f + expf(-g[1])) * u[1];
                    __nv_bfloat16 a,bb,c,dd;
                    f2bf2(h0, a, c); f2bf2(h1, bb, dd);
                    __nv_bfloat162 vh; vh.x = a;  vh.y = bb;
                    __nv_bfloat162 vl; vl.x = c;  vl.y = dd;
                    *(__nv_bfloat162*)(g_h_hi + rowA * INTER + col) = vh;
                    *(__nv_bfloat162*)(g_h_lo + rowA * INTER + col) = vl;
                }
                if (vB) {
                    float h0 = g[2] / (1.f + expf(-g[2])) * u[2];
                    float h1 = g[3] / (1.f + expf(-g[3])) * u[3];
                    __nv_bfloat16 a,bb,c,dd;
                    f2bf2(h0, a, c); f2bf2(h1, bb, dd);
                    __nv_bfloat162 vh; vh.x = a;  vh.y = bb;
                    __nv_bfloat162 vl; vl.x = c;  vl.y = dd;
                    *(__nv_bfloat162*)(g_h_hi + rowB * INTER + col) = vh;
                    *(__nv_bfloat162*)(g_h_lo + rowB * INTER + col) = vl;
                }
            }
        }
    } else {
#pragma unroll
        for (int mi = 0; mi < 2; mi++) {
            int rA = warp_m + mi * 16 + (lid >> 2);
            int rB = rA + 8;
            bool vA = (m0 + rA) < cnt;
            bool vB = (m0 + rB) < cnt;
            float* cA = g_ct + (size_t)(off_e + m0 + rA) * D_HID + n0 + warp_n + (lid & 3) * 2;
            float* cB = g_ct + (size_t)(off_e + m0 + rB) * D_HID + n0 + warp_n + (lid & 3) * 2;
#pragma unroll
            for (int ni = 0; ni < 8; ni++) {
                if (vA) { float2 v; v.x = d[mi][ni][0]; v.y = d[mi][ni][1];
                          *(float2*)(cA + ni * 8) = v; }
                if (vB) { float2 v; v.x = d[mi][ni][2]; v.y = d[mi][ni][3];
                          *(float2*)(cB + ni * 8) = v; }
            }
        }
    }
}

// ---------------- combine ----------------
__global__ void combine_kernel(float* __restrict__ out, int total4) {
    int i = blockIdx.x * blockDim.x + threadIdx.x;
    if (i >= total4) return;
    int c = i % (D_HID/4);
    int t = i / (D_HID/4);
    float w0 = g_wt[2*t], w1 = g_wt[2*t+1];
    int s0 = g_p2s[2*t], s1 = g_p2s[2*t+1];
    float4 c0 = ((const float4*)(g_ct + (size_t)s0 * D_HID))[c];
    float4 c1 = ((const float4*)(g_ct + (size_t)s1 * D_HID))[c];
    float4 o;
    o.x = fmaf(w0, c0.x, w1 * c1.x);
    o.y = fmaf(w0, c0.y, w1 * c1.y);
    o.z = fmaf(w0, c0.z, w1 * c1.z);
    o.w = fmaf(w0, c0.w, w1 * c1.w);
    ((float4*)out)[i] = o;
}

// ---------------- launch ----------------
extern "C" void kernel_launch(void* const* d_in, const int* in_sizes, int n_in,
                              void* d_out, int out_size) {
    const float* x   = (const float*)d_in[0];
    const float* rw  = (const float*)d_in[1];
    const float* gup = (const float*)d_in[2];
    const float* dwn = (const float*)d_in[3];
    float* out = (float*)d_out;
    int T = in_sizes[0] / D_HID;

    cudaFuncSetAttribute(moe_gemm_kernel<0>, cudaFuncAttributeMaxDynamicSharedMemorySize, GEMM_SMEM);
    cudaFuncSetAttribute(moe_gemm_kernel<1>, cudaFuncAttributeMaxDynamicSharedMemorySize, GEMM_SMEM);

    zero_counts_kernel<<<1, 32>>>();                       // 0
    router_kernel<<<T, 256>>>(x, rw);                      // 1
    int prep_blocks = TPAIR + NEXP * NGU + NEXP * D_HID;
    prep_kernel<<<prep_blocks, 128>>>(x, gup, dwn);        // 2

    dim3 g0(32, NGU / 256, NEXP);                          // 3 (GEMM1 @ index 3)
    moe_gemm_kernel<0><<<g0, 512, GEMM_SMEM>>>();

    dim3 g1(32, D_HID / 256, NEXP);                        // 4
    moe_gemm_kernel<1><<<g1, 512, GEMM_SMEM>>>();

    combine_kernel<<<(T * (D_HID/4) + 255) / 256, 256>>>(out, T * (D_HID/4)); // 5
}

// round 6
// speedup vs baseline: 1.4331x; 1.4331x over previous
#include <cuda_runtime.h>
#include <cuda_fp16.h>
#include <cstdint>
#include <math.h>

#define D_HID 2048
#define INTER 1408
#define NGU   2816
#define NEXP  8
#define TMAX  4096
#define TPAIR 8192
#define RMAX  9216

// ---------------- device scratch ----------------
__device__ int   g_count[NEXP];
__device__ int   g_top_e[TPAIR];
__device__ int   g_pos[TPAIR];
__device__ int   g_p2s[TPAIR];
__device__ float g_wt[TPAIR];
__device__ __align__(256) __half g_xg_hi [(size_t)RMAX * D_HID];
__device__ __align__(256) __half g_xg_lo [(size_t)RMAX * D_HID];
__device__ __align__(256) __half g_gup   [(size_t)NEXP * NGU * D_HID];
__device__ __align__(256) __half g_dwn   [(size_t)NEXP * D_HID * INTER];
__device__ __align__(256) __half g_h_hi  [(size_t)RMAX * INTER];
__device__ __align__(256) __half g_h_lo  [(size_t)RMAX * INTER];
__device__ __align__(256) float  g_ct    [(size_t)RMAX * D_HID];

// ---------------- helpers ----------------
__device__ __forceinline__ uint32_t smem_u32(const void* p) {
    uint32_t a;
    asm("{ .reg .u64 t; cvta.to.shared.u64 t, %1; cvt.u32.u64 %0, t; }" : "=r"(a) : "l"(p));
    return a;
}
__device__ __forceinline__ void cp16z(uint32_t dst, const void* src, uint32_t sz) {
    asm volatile("cp.async.cg.shared.global [%0], [%1], 16, %2;"
                 :: "r"(dst), "l"(src), "r"(sz));
}
__device__ __forceinline__ void ldsm4(uint32_t* r, uint32_t addr) {
    asm volatile("ldmatrix.sync.aligned.m8n8.x4.shared.b16 {%0,%1,%2,%3}, [%4];"
                 : "=r"(r[0]), "=r"(r[1]), "=r"(r[2]), "=r"(r[3]) : "r"(addr));
}
__device__ __forceinline__ void mma_f16(float* d, const uint32_t* a, const uint32_t* b) {
    asm volatile("mma.sync.aligned.m16n8k16.row.col.f32.f16.f16.f32 "
                 "{%0,%1,%2,%3}, {%4,%5,%6,%7}, {%8,%9}, {%0,%1,%2,%3};"
                 : "+f"(d[0]), "+f"(d[1]), "+f"(d[2]), "+f"(d[3])
                 : "r"(a[0]), "r"(a[1]), "r"(a[2]), "r"(a[3]), "r"(b[0]), "r"(b[1]));
}
__device__ __forceinline__ void f2h2(float x, __half& hi, __half& lo) {
    hi = __float2half(x);
    lo = __float2half(x - __half2float(hi));
}
__device__ __forceinline__ int expert_base(int e) {
    int o = 0;
#pragma unroll
    for (int k = 0; k < NEXP; k++)
        if (k < e) o += (g_count[k] + 127) & ~127;
    return o;
}

// ---------------- init ----------------
__global__ void zero_counts_kernel() {
    if (threadIdx.x < NEXP) g_count[threadIdx.x] = 0;
}

// ---------------- router ----------------
__global__ void router_kernel(const float* __restrict__ x,
                              const float* __restrict__ rw) {
    int t = blockIdx.x;
    const float* xr = x + (size_t)t * D_HID;
    float p[NEXP];
#pragma unroll
    for (int e = 0; e < NEXP; e++) p[e] = 0.f;
    for (int d = threadIdx.x; d < D_HID; d += blockDim.x) {
        float xv = xr[d];
#pragma unroll
        for (int e = 0; e < NEXP; e++)
            p[e] = fmaf(xv, rw[e * D_HID + d], p[e]);
    }
#pragma unroll
    for (int off = 16; off > 0; off >>= 1)
#pragma unroll
        for (int e = 0; e < NEXP; e++)
            p[e] += __shfl_down_sync(0xffffffffu, p[e], off);
    __shared__ float s[8][NEXP];
    int warp = threadIdx.x >> 5;
    if ((threadIdx.x & 31) == 0)
#pragma unroll
        for (int e = 0; e < NEXP; e++) s[warp][e] = p[e];
    __syncthreads();
    if (threadIdx.x == 0) {
        float l[NEXP];
#pragma unroll
        for (int e = 0; e < NEXP; e++) {
            float a = 0.f;
#pragma unroll
            for (int w = 0; w < 8; w++) a += s[w][e];
            l[e] = a;
        }
        int i0 = 0;
#pragma unroll
        for (int e = 1; e < NEXP; e++) if (l[e] > l[i0]) i0 = e;
        int i1 = (i0 == 0) ? 1 : 0;
#pragma unroll
        for (int e = 0; e < NEXP; e++)
            if (e != i0 && l[e] > l[i1]) i1 = e;
        float e1  = expf(l[i1] - l[i0]);
        float inv = 1.f / (1.f + e1);
        g_wt[2*t]   = inv;
        g_wt[2*t+1] = e1 * inv;
        int p0 = atomicAdd(&g_count[i0], 1);
        g_top_e[2*t] = i0; g_pos[2*t] = p0;
        int p1 = atomicAdd(&g_count[i1], 1);
        g_top_e[2*t+1] = i1; g_pos[2*t+1] = p1;
    }
}

// ---------------- prep: gather-x (fp16 hi/lo) + weight fp16 conversions -----
__global__ void prep_kernel(const float* __restrict__ x,
                            const float* __restrict__ gup,
                            const float* __restrict__ dwn) {
    int b = blockIdx.x;
    if (b < TPAIR) {
        int p = b;
        int t = p >> 1;
        int s = expert_base(g_top_e[p]) + g_pos[p];
        if (threadIdx.x == 0) g_p2s[p] = s;
        const float4* src = (const float4*)(x + (size_t)t * D_HID);
        __half2* dh = (__half2*)(g_xg_hi + (size_t)s * D_HID);
        __half2* dl = (__half2*)(g_xg_lo + (size_t)s * D_HID);
        for (int i = threadIdx.x; i < D_HID/4; i += blockDim.x) {
            float4 v = src[i];
            __half h0,l0,h1,l1,h2,l2,h3,l3;
            f2h2(v.x,h0,l0); f2h2(v.y,h1,l1); f2h2(v.z,h2,l2); f2h2(v.w,h3,l3);
            dh[2*i]   = __halves2half2(h0, h1);
            dh[2*i+1] = __halves2half2(h2, h3);
            dl[2*i]   = __halves2half2(l0, l1);
            dl[2*i+1] = __halves2half2(l2, l3);
        }
    } else if (b < TPAIR + NEXP * NGU) {
        int row = b - TPAIR;
        int e = row / NGU;
        int n = row % NGU;
        int blk = n >> 6, r = n & 63;
        int src_n = (r < 32) ? (blk*32 + r) : (INTER + blk*32 + (r - 32));
        const float4* src = (const float4*)(gup + ((size_t)e * NGU + src_n) * D_HID);
        __half2* dh = (__half2*)(g_gup + (size_t)row * D_HID);
        for (int i = threadIdx.x; i < D_HID/4; i += blockDim.x) {
            float4 v = src[i];
            dh[2*i]   = __halves2half2(__float2half(v.x), __float2half(v.y));
            dh[2*i+1] = __halves2half2(__float2half(v.z), __float2half(v.w));
        }
    } else {
        int row = b - TPAIR - NEXP * NGU;
        const float4* src = (const float4*)(dwn + (size_t)row * INTER);
        __half2* dh = (__half2*)(g_dwn + (size_t)row * INTER);
        for (int i = threadIdx.x; i < INTER/4; i += blockDim.x) {
            float4 v = src[i];
            dh[2*i]   = __halves2half2(__float2half(v.x), __float2half(v.y));
            dh[2*i+1] = __halves2half2(__float2half(v.z), __float2half(v.w));
        }
    }
}

// ---------------- HMMA grouped GEMM (fp16 asym split-2), CTA 128x256 --------
#define PITCH 80
#define A_TILE (128*PITCH)           // 10240
#define B_TILE (256*PITCH)           // 20480
#define AH_OFF 0
#define AL_OFF A_TILE
#define B_OFF  (2*A_TILE)
#define STAGE  (2*A_TILE + B_TILE)   // 40960
#define NSTG   4
#define GEMM_SMEM (NSTG*STAGE)       // 163840

template <int PHASE>
__global__ void __launch_bounds__(512, 1)
moe_gemm_kernel() {
    constexpr int Kd  = (PHASE == 0) ? D_HID : INTER;   // 2048 / 1408
    constexpr int NCH = Kd / 32;                        // 64 / 44
    constexpr int NROW = (PHASE == 0) ? NGU : D_HID;

    int e   = blockIdx.z;
    int cnt = g_count[e];
    int m0  = blockIdx.x * 128;
    if (m0 >= cnt) return;
    int n0  = blockIdx.y * 256;
    int off_e = expert_base(e);

    const __half* Ahi = ((PHASE == 0) ? g_xg_hi : g_h_hi) + (size_t)(off_e + m0) * Kd;
    const __half* Alo = ((PHASE == 0) ? g_xg_lo : g_h_lo) + (size_t)(off_e + m0) * Kd;
    const __half* B   = ((PHASE == 0) ? g_gup   : g_dwn ) + ((size_t)e * NROW + n0) * Kd;

    extern __shared__ __align__(128) char smem[];
    uint32_t sb = smem_u32(smem);

    int tid = threadIdx.x;
    int wid = tid >> 5;
    int lid = tid & 31;
    int warp_m = (wid >> 2) * 32;
    int warp_n = (wid & 3) * 64;

    // cp.async: A hi/lo 1 op each (128 rows x 4 quads = 512), B 2 ops (1024)
    int ra  = tid >> 2, qa = tid & 3;
    uint32_t soA  = (uint32_t)(ra * PITCH + qa * 16);
    uint32_t soB1 = (uint32_t)((ra + 128) * PITCH + qa * 16);
    const char* pAh = (const char*)(Ahi + (size_t)ra * Kd + qa * 8);
    const char* pAl = (const char*)(Alo + (size_t)ra * Kd + qa * 8);
    const char* pB0 = (const char*)(B   + (size_t)ra * Kd + qa * 8);
    const char* pB1 = (const char*)(B   + (size_t)(ra + 128) * Kd + qa * 8);
    uint32_t szA = (m0 + ra < cnt) ? 16u : 0u;

    uint32_t a_off = (uint32_t)((warp_m + (lid & 15)) * PITCH + (lid >> 4) * 16);
    uint32_t b_off = (uint32_t)((warp_n + (lid & 7) + ((lid & 16) >> 1)) * PITCH +
                                ((lid >> 3) & 1) * 16);

    float d[2][8][4];
#pragma unroll
    for (int mi = 0; mi < 2; mi++)
#pragma unroll
        for (int ni = 0; ni < 8; ni++)
#pragma unroll
            for (int k = 0; k < 4; k++) d[mi][ni][k] = 0.f;

    auto load_chunk = [&](int ci, int s) {
        uint32_t st = sb + s * STAGE;
        size_t go = (size_t)ci * 64;   // 32 fp16 = 64 bytes along K
        cp16z(st + AH_OFF + soA, pAh + go, szA);
        cp16z(st + AL_OFF + soA, pAl + go, szA);
        cp16z(st + B_OFF  + soA, pB0 + go, 16u);
        cp16z(st + B_OFF  + soB1, pB1 + go, 16u);
    };

#pragma unroll
    for (int s = 0; s < NSTG - 1; s++) {
        load_chunk(s, s);
        asm volatile("cp.async.commit_group;" ::: "memory");
    }

#pragma unroll 1
    for (int i = 0; i < NCH; i++) {
        asm volatile("cp.async.wait_group 2;" ::: "memory");
        __syncthreads();
        if (i + NSTG - 1 < NCH) load_chunk(i + NSTG - 1, (i + NSTG - 1) & (NSTG - 1));
        asm volatile("cp.async.commit_group;" ::: "memory");

        uint32_t st = sb + (i & (NSTG - 1)) * STAGE;
#pragma unroll
        for (int kk = 0; kk < 2; kk++) {
            uint32_t ko = kk * 32;
            uint32_t ah[2][4], al[2][4];
            ldsm4(ah[0], st + AH_OFF + a_off + ko);
            ldsm4(ah[1], st + AH_OFF + a_off + ko + 16 * PITCH);
            ldsm4(al[0], st + AL_OFF + a_off + ko);
            ldsm4(al[1], st + AL_OFF + a_off + ko + 16 * PITCH);
#pragma unroll
            for (int pp = 0; pp < 2; pp++) {
                uint32_t bf[2][4];
                ldsm4(bf[0], st + B_OFF + b_off + ko + (pp*2 + 0) * 16 * PITCH);
                ldsm4(bf[1], st + B_OFF + b_off + ko + (pp*2 + 1) * 16 * PITCH);
#pragma unroll
                for (int mi = 0; mi < 2; mi++)
#pragma unroll
                    for (int q = 0; q < 4; q++)
                        mma_f16(d[mi][pp*4 + q], ah[mi], &bf[q >> 1][(q & 1) * 2]);
#pragma unroll
                for (int mi = 0; mi < 2; mi++)
#pragma unroll
                    for (int q = 0; q < 4; q++)
                        mma_f16(d[mi][pp*4 + q], al[mi], &bf[q >> 1][(q & 1) * 2]);
            }
        }
    }

    // ---------------- epilogue ----------------
    if (PHASE == 0) {
        int icb = blockIdx.y * 128 + (warp_n >> 1);
#pragma unroll
        for (int mi = 0; mi < 2; mi++) {
            int rA = warp_m + mi * 16 + (lid >> 2);
            int rB = rA + 8;
            bool vA = (m0 + rA) < cnt;
            bool vB = (m0 + rB) < cnt;
            size_t rowA = (size_t)(off_e + m0 + rA);
            size_t rowB = (size_t)(off_e + m0 + rB);
#pragma unroll
            for (int ni = 0; ni < 4; ni++) {
                int col = icb + ni * 8 + (lid & 3) * 2;
                const float* g = d[mi][ni];
                const float* u = d[mi][ni + 4];
                if (vA) {
                    float h0 = g[0] / (1.f + expf(-g[0])) * u[0];
                    float h1 = g[1] / (1.f + expf(-g[1])) * u[1];
                    __half a,bb,c,dd;
                    f2h2(h0, a, c); f2h2(h1, bb, dd);
                    *(__half2*)(g_h_hi + rowA * INTER + col) = __halves2half2(a, bb);
                    *(__half2*)(g_h_lo + rowA * INTER + col) = __halves2half2(c, dd);
                }
                if (vB) {
                    float h0 = g[2] / (1.f + expf(-g[2])) * u[2];
                    float h1 = g[3] / (1.f + expf(-g[3])) * u[3];
                    __half a,bb,c,dd;
                    f2h2(h0, a, c); f2h2(h1, bb, dd);
                    *(__half2*)(g_h_hi + rowB * INTER + col) = __halves2half2(a, bb);
                    *(__half2*)(g_h_lo + rowB * INTER + col) = __halves2half2(c, dd);
                }
            }
        }
    } else {
#pragma unroll
        for (int mi = 0; mi < 2; mi++) {
            int rA = warp_m + mi * 16 + (lid >> 2);
            int rB = rA + 8;
            bool vA = (m0 + rA) < cnt;
            bool vB = (m0 + rB) < cnt;
            float* cA = g_ct + (size_t)(off_e + m0 + rA) * D_HID + n0 + warp_n + (lid & 3) * 2;
            float* cB = g_ct + (size_t)(off_e + m0 + rB) * D_HID + n0 + warp_n + (lid & 3) * 2;
#pragma unroll
            for (int ni = 0; ni < 8; ni++) {
                if (vA) { float2 v; v.x = d[mi][ni][0]; v.y = d[mi][ni][1];
                          *(float2*)(cA + ni * 8) = v; }
                if (vB) { float2 v; v.x = d[mi][ni][2]; v.y = d[mi][ni][3];
                          *(float2*)(cB + ni * 8) = v; }
            }
        }
    }
}

// ---------------- combine ----------------
__global__ void combine_kernel(float* __restrict__ out, int total4) {
    int i = blockIdx.x * blockDim.x + threadIdx.x;
    if (i >= total4) return;
    int c = i % (D_HID/4);
    int t = i / (D_HID/4);
    float w0 = g_wt[2*t], w1 = g_wt[2*t+1];
    int s0 = g_p2s[2*t], s1 = g_p2s[2*t+1];
    float4 c0 = ((const float4*)(g_ct + (size_t)s0 * D_HID))[c];
    float4 c1 = ((const float4*)(g_ct + (size_t)s1 * D_HID))[c];
    float4 o;
    o.x = fmaf(w0, c0.x, w1 * c1.x);
    o.y = fmaf(w0, c0.y, w1 * c1.y);
    o.z = fmaf(w0, c0.z, w1 * c1.z);
    o.w = fmaf(w0, c0.w, w1 * c1.w);
    ((float4*)out)[i] = o;
}

// ---------------- launch ----------------
extern "C" void kernel_launch(void* const* d_in, const int* in_sizes, int n_in,
                              void* d_out, int out_size) {
    const float* x   = (const float*)d_in[0];
    const float* rw  = (const float*)d_in[1];
    const float* gup = (const float*)d_in[2];
    const float* dwn = (const float*)d_in[3];
    float* out = (float*)d_out;
    int T = in_sizes[0] / D_HID;

    cudaFuncSetAttribute(moe_gemm_kernel<0>, cudaFuncAttributeMaxDynamicSharedMemorySize, GEMM_SMEM);
    cudaFuncSetAttribute(moe_gemm_kernel<1>, cudaFuncAttributeMaxDynamicSharedMemorySize, GEMM_SMEM);

    zero_counts_kernel<<<1, 32>>>();                       // 0
    router_kernel<<<T, 256>>>(x, rw);                      // 1
    int prep_blocks = TPAIR + NEXP * NGU + NEXP * D_HID;
    prep_kernel<<<prep_blocks, 128>>>(x, gup, dwn);        // 2

    dim3 g0(32, NGU / 256, NEXP);                          // 3 (GEMM1 @ index 3)
    moe_gemm_kernel<0><<<g0, 512, GEMM_SMEM>>>();

    dim3 g1(32, D_HID / 256, NEXP);                        // 4
    moe_gemm_kernel<1><<<g1, 512, GEMM_SMEM>>>();

    combine_kernel<<<(T * (D_HID/4) + 255) / 256, 256>>>(out, T * (D_HID/4)); // 5
}

// round 7
// speedup vs baseline: 1.4797x; 1.0325x over previous
#include <cuda_runtime.h>
#include <cuda_fp16.h>
#include <cstdint>
#include <math.h>

#define D_HID 2048
#define INTER 1408
#define NGU   2816
#define NEXP  8
#define TMAX  4096
#define TPAIR 8192
#define RMAX  9216

// ---------------- device scratch ----------------
__device__ int   g_count[NEXP];
__device__ int   g_top_e[TPAIR];
__device__ int   g_pos[TPAIR];
__device__ int   g_p2s[TPAIR];
__device__ float g_wt[TPAIR];
__device__ __align__(256) __half g_xg_hi [(size_t)RMAX * D_HID];
__device__ __align__(256) __half g_xg_lo [(size_t)RMAX * D_HID];
__device__ __align__(256) __half g_gup   [(size_t)NEXP * NGU * D_HID];
__device__ __align__(256) __half g_dwn   [(size_t)NEXP * D_HID * INTER];
__device__ __align__(256) __half g_h_hi  [(size_t)RMAX * INTER];
__device__ __align__(256) __half g_h_lo  [(size_t)RMAX * INTER];
__device__ __align__(256) float  g_ct    [(size_t)RMAX * D_HID];

// ---------------- helpers ----------------
__device__ __forceinline__ uint32_t smem_u32(const void* p) {
    uint32_t a;
    asm("{ .reg .u64 t; cvta.to.shared.u64 t, %1; cvt.u32.u64 %0, t; }" : "=r"(a) : "l"(p));
    return a;
}
__device__ __forceinline__ void cp16z(uint32_t dst, const void* src, uint32_t sz) {
    asm volatile("cp.async.cg.shared.global [%0], [%1], 16, %2;"
                 :: "r"(dst), "l"(src), "r"(sz));
}
__device__ __forceinline__ void ldsm4(uint32_t* r, uint32_t addr) {
    asm volatile("ldmatrix.sync.aligned.m8n8.x4.shared.b16 {%0,%1,%2,%3}, [%4];"
                 : "=r"(r[0]), "=r"(r[1]), "=r"(r[2]), "=r"(r[3]) : "r"(addr));
}
__device__ __forceinline__ void mma_f16(float* d, const uint32_t* a, const uint32_t* b) {
    asm volatile("mma.sync.aligned.m16n8k16.row.col.f32.f16.f16.f32 "
                 "{%0,%1,%2,%3}, {%4,%5,%6,%7}, {%8,%9}, {%0,%1,%2,%3};"
                 : "+f"(d[0]), "+f"(d[1]), "+f"(d[2]), "+f"(d[3])
                 : "r"(a[0]), "r"(a[1]), "r"(a[2]), "r"(a[3]), "r"(b[0]), "r"(b[1]));
}
__device__ __forceinline__ void f2h2(float x, __half& hi, __half& lo) {
    hi = __float2half(x);
    lo = __float2half(x - __half2float(hi));
}
__device__ __forceinline__ int expert_base(int e) {
    int o = 0;
#pragma unroll
    for (int k = 0; k < NEXP; k++)
        if (k < e) o += (g_count[k] + 127) & ~127;
    return o;
}

// ---------------- init ----------------
__global__ void zero_counts_kernel() {
    if (threadIdx.x < NEXP) g_count[threadIdx.x] = 0;
}

// ---------------- router ----------------
__global__ void router_kernel(const float* __restrict__ x,
                              const float* __restrict__ rw) {
    int t = blockIdx.x;
    const float* xr = x + (size_t)t * D_HID;
    float p[NEXP];
#pragma unroll
    for (int e = 0; e < NEXP; e++) p[e] = 0.f;
    for (int d = threadIdx.x; d < D_HID; d += blockDim.x) {
        float xv = xr[d];
#pragma unroll
        for (int e = 0; e < NEXP; e++)
            p[e] = fmaf(xv, rw[e * D_HID + d], p[e]);
    }
#pragma unroll
    for (int off = 16; off > 0; off >>= 1)
#pragma unroll
        for (int e = 0; e < NEXP; e++)
            p[e] += __shfl_down_sync(0xffffffffu, p[e], off);
    __shared__ float s[8][NEXP];
    int warp = threadIdx.x >> 5;
    if ((threadIdx.x & 31) == 0)
#pragma unroll
        for (int e = 0; e < NEXP; e++) s[warp][e] = p[e];
    __syncthreads();
    if (threadIdx.x == 0) {
        float l[NEXP];
#pragma unroll
        for (int e = 0; e < NEXP; e++) {
            float a = 0.f;
#pragma unroll
            for (int w = 0; w < 8; w++) a += s[w][e];
            l[e] = a;
        }
        int i0 = 0;
#pragma unroll
        for (int e = 1; e < NEXP; e++) if (l[e] > l[i0]) i0 = e;
        int i1 = (i0 == 0) ? 1 : 0;
#pragma unroll
        for (int e = 0; e < NEXP; e++)
            if (e != i0 && l[e] > l[i1]) i1 = e;
        float e1  = expf(l[i1] - l[i0]);
        float inv = 1.f / (1.f + e1);
        g_wt[2*t]   = inv;
        g_wt[2*t+1] = e1 * inv;
        int p0 = atomicAdd(&g_count[i0], 1);
        g_top_e[2*t] = i0; g_pos[2*t] = p0;
        int p1 = atomicAdd(&g_count[i1], 1);
        g_top_e[2*t+1] = i1; g_pos[2*t+1] = p1;
    }
}

// ---------------- prep: gather-x (fp16 hi/lo) + weight fp16 conversions -----
__global__ void prep_kernel(const float* __restrict__ x,
                            const float* __restrict__ gup,
                            const float* __restrict__ dwn) {
    int b = blockIdx.x;
    if (b < TPAIR) {
        int p = b;
        int t = p >> 1;
        int s = expert_base(g_top_e[p]) + g_pos[p];
        if (threadIdx.x == 0) g_p2s[p] = s;
        const float4* src = (const float4*)(x + (size_t)t * D_HID);
        __half2* dh = (__half2*)(g_xg_hi + (size_t)s * D_HID);
        __half2* dl = (__half2*)(g_xg_lo + (size_t)s * D_HID);
        for (int i = threadIdx.x; i < D_HID/4; i += blockDim.x) {
            float4 v = src[i];
            __half h0,l0,h1,l1,h2,l2,h3,l3;
            f2h2(v.x,h0,l0); f2h2(v.y,h1,l1); f2h2(v.z,h2,l2); f2h2(v.w,h3,l3);
            dh[2*i]   = __halves2half2(h0, h1);
            dh[2*i+1] = __halves2half2(h2, h3);
            dl[2*i]   = __halves2half2(l0, l1);
            dl[2*i+1] = __halves2half2(l2, l3);
        }
    } else if (b < TPAIR + NEXP * NGU) {
        int row = b - TPAIR;
        int e = row / NGU;
        int n = row % NGU;
        int blk = n >> 6, r = n & 63;
        int src_n = (r < 32) ? (blk*32 + r) : (INTER + blk*32 + (r - 32));
        const float4* src = (const float4*)(gup + ((size_t)e * NGU + src_n) * D_HID);
        __half2* dh = (__half2*)(g_gup + (size_t)row * D_HID);
        for (int i = threadIdx.x; i < D_HID/4; i += blockDim.x) {
            float4 v = src[i];
            dh[2*i]   = __halves2half2(__float2half(v.x), __float2half(v.y));
            dh[2*i+1] = __halves2half2(__float2half(v.z), __float2half(v.w));
        }
    } else {
        int row = b - TPAIR - NEXP * NGU;
        const float4* src = (const float4*)(dwn + (size_t)row * INTER);
        __half2* dh = (__half2*)(g_dwn + (size_t)row * INTER);
        for (int i = threadIdx.x; i < INTER/4; i += blockDim.x) {
            float4 v = src[i];
            dh[2*i]   = __halves2half2(__float2half(v.x), __float2half(v.y));
            dh[2*i+1] = __halves2half2(__float2half(v.z), __float2half(v.w));
        }
    }
}

// ---------------- HMMA grouped GEMM (fp16 asym split-2) ---------------------
// CTA tile 128x128, 256 threads (8 warps: 4 in M x 2 in N), 2 CTAs/SM
#define PITCH 80
#define A_TILE (128*PITCH)           // 10240
#define B_TILE (128*PITCH)           // 10240
#define AH_OFF 0
#define AL_OFF A_TILE
#define B_OFF  (2*A_TILE)
#define STAGE  (2*A_TILE + B_TILE)   // 30720
#define NSTG   3
#define GEMM_SMEM (NSTG*STAGE)       // 92160

template <int PHASE>
__global__ void __launch_bounds__(256, 2)
moe_gemm_kernel() {
    constexpr int Kd  = (PHASE == 0) ? D_HID : INTER;   // 2048 / 1408
    constexpr int NCH = Kd / 32;                        // 64 / 44
    constexpr int NROW = (PHASE == 0) ? NGU : D_HID;

    int e   = blockIdx.z;
    int cnt = g_count[e];
    int m0  = blockIdx.x * 128;
    if (m0 >= cnt) return;
    int n0  = blockIdx.y * 128;
    int off_e = expert_base(e);

    const __half* Ahi = ((PHASE == 0) ? g_xg_hi : g_h_hi) + (size_t)(off_e + m0) * Kd;
    const __half* Alo = ((PHASE == 0) ? g_xg_lo : g_h_lo) + (size_t)(off_e + m0) * Kd;
    const __half* B   = ((PHASE == 0) ? g_gup   : g_dwn ) + ((size_t)e * NROW + n0) * Kd;

    extern __shared__ __align__(128) char smem[];
    uint32_t sb = smem_u32(smem);

    int tid = threadIdx.x;
    int wid = tid >> 5;
    int lid = tid & 31;
    int warp_m = (wid >> 1) * 32;     // 0,32,64,96
    int warp_n = (wid & 1) * 64;      // 0,64

    // cp.async: 256 threads; each tile (128 rows x 4 quads = 512 ops) -> 2/thread
    int r0 = tid >> 2, qa = tid & 3;
    int r1 = r0 + 64;
    uint32_t so0 = (uint32_t)(r0 * PITCH + qa * 16);
    uint32_t so1 = (uint32_t)(r1 * PITCH + qa * 16);
    const char* pAh0 = (const char*)(Ahi + (size_t)r0 * Kd + qa * 8);
    const char* pAh1 = (const char*)(Ahi + (size_t)r1 * Kd + qa * 8);
    const char* pAl0 = (const char*)(Alo + (size_t)r0 * Kd + qa * 8);
    const char* pAl1 = (const char*)(Alo + (size_t)r1 * Kd + qa * 8);
    const char* pB0  = (const char*)(B   + (size_t)r0 * Kd + qa * 8);
    const char* pB1  = (const char*)(B   + (size_t)r1 * Kd + qa * 8);
    uint32_t szA0 = (m0 + r0 < cnt) ? 16u : 0u;
    uint32_t szA1 = (m0 + r1 < cnt) ? 16u : 0u;

    uint32_t a_off = (uint32_t)((warp_m + (lid & 15)) * PITCH + (lid >> 4) * 16);
    uint32_t b_off = (uint32_t)((warp_n + (lid & 7) + ((lid & 16) >> 1)) * PITCH +
                                ((lid >> 3) & 1) * 16);

    float d[2][8][4];
#pragma unroll
    for (int mi = 0; mi < 2; mi++)
#pragma unroll
        for (int ni = 0; ni < 8; ni++)
#pragma unroll
            for (int k = 0; k < 4; k++) d[mi][ni][k] = 0.f;

    auto load_chunk = [&](int ci, int s) {
        uint32_t st = sb + s * STAGE;
        size_t go = (size_t)ci * 64;   // 32 fp16 = 64 B along K
        cp16z(st + AH_OFF + so0, pAh0 + go, szA0);
        cp16z(st + AH_OFF + so1, pAh1 + go, szA1);
        cp16z(st + AL_OFF + so0, pAl0 + go, szA0);
        cp16z(st + AL_OFF + so1, pAl1 + go, szA1);
        cp16z(st + B_OFF  + so0, pB0  + go, 16u);
        cp16z(st + B_OFF  + so1, pB1  + go, 16u);
    };

    load_chunk(0, 0);
    asm volatile("cp.async.commit_group;" ::: "memory");
    load_chunk(1, 1);
    asm volatile("cp.async.commit_group;" ::: "memory");

    int sidx = 0, lidx = 2;
#pragma unroll 1
    for (int i = 0; i < NCH; i++) {
        asm volatile("cp.async.wait_group 1;" ::: "memory");
        __syncthreads();
        if (i + 2 < NCH) load_chunk(i + 2, lidx);
        asm volatile("cp.async.commit_group;" ::: "memory");

        uint32_t st = sb + sidx * STAGE;
#pragma unroll
        for (int kk = 0; kk < 2; kk++) {
            uint32_t ko = kk * 32;
            uint32_t ah[2][4], al[2][4];
            ldsm4(ah[0], st + AH_OFF + a_off + ko);
            ldsm4(ah[1], st + AH_OFF + a_off + ko + 16 * PITCH);
            ldsm4(al[0], st + AL_OFF + a_off + ko);
            ldsm4(al[1], st + AL_OFF + a_off + ko + 16 * PITCH);
#pragma unroll
            for (int pp = 0; pp < 2; pp++) {
                uint32_t bf[2][4];
                ldsm4(bf[0], st + B_OFF + b_off + ko + (pp*2 + 0) * 16 * PITCH);
                ldsm4(bf[1], st + B_OFF + b_off + ko + (pp*2 + 1) * 16 * PITCH);
#pragma unroll
                for (int mi = 0; mi < 2; mi++)
#pragma unroll
                    for (int q = 0; q < 4; q++)
                        mma_f16(d[mi][pp*4 + q], ah[mi], &bf[q >> 1][(q & 1) * 2]);
#pragma unroll
                for (int mi = 0; mi < 2; mi++)
#pragma unroll
                    for (int q = 0; q < 4; q++)
                        mma_f16(d[mi][pp*4 + q], al[mi], &bf[q >> 1][(q & 1) * 2]);
            }
        }
        sidx = (sidx == NSTG-1) ? 0 : sidx + 1;
        lidx = (lidx == NSTG-1) ? 0 : lidx + 1;
    }

    // ---------------- epilogue ----------------
    if (PHASE == 0) {
        int icb = blockIdx.y * 64 + (warp_n >> 1);
#pragma unroll
        for (int mi = 0; mi < 2; mi++) {
            int rA = warp_m + mi * 16 + (lid >> 2);
            int rB = rA + 8;
            bool vA = (m0 + rA) < cnt;
            bool vB = (m0 + rB) < cnt;
            size_t rowA = (size_t)(off_e + m0 + rA);
            size_t rowB = (size_t)(off_e + m0 + rB);
#pragma unroll
            for (int ni = 0; ni < 4; ni++) {
                int col = icb + ni * 8 + (lid & 3) * 2;
                const float* g = d[mi][ni];
                const float* u = d[mi][ni + 4];
                if (vA) {
                    float h0 = g[0] / (1.f + expf(-g[0])) * u[0];
                    float h1 = g[1] / (1.f + expf(-g[1])) * u[1];
                    __half a,bb,c,dd;
                    f2h2(h0, a, c); f2h2(h1, bb, dd);
                    *(__half2*)(g_h_hi + rowA * INTER + col) = __halves2half2(a, bb);
                    *(__half2*)(g_h_lo + rowA * INTER + col) = __halves2half2(c, dd);
                }
                if (vB) {
                    float h0 = g[2] / (1.f + expf(-g[2])) * u[2];
                    float h1 = g[3] / (1.f + expf(-g[3])) * u[3];
                    __half a,bb,c,dd;
                    f2h2(h0, a, c); f2h2(h1, bb, dd);
                    *(__half2*)(g_h_hi + rowB * INTER + col) = __halves2half2(a, bb);
                    *(__half2*)(g_h_lo + rowB * INTER + col) = __halves2half2(c, dd);
                }
            }
        }
    } else {
#pragma unroll
        for (int mi = 0; mi < 2; mi++) {
            int rA = warp_m + mi * 16 + (lid >> 2);
            int rB = rA + 8;
            bool vA = (m0 + rA) < cnt;
            bool vB = (m0 + rB) < cnt;
            float* cA = g_ct + (size_t)(off_e + m0 + rA) * D_HID + n0 + warp_n + (lid & 3) * 2;
            float* cB = g_ct + (size_t)(off_e + m0 + rB) * D_HID + n0 + warp_n + (lid & 3) * 2;
#pragma unroll
            for (int ni = 0; ni < 8; ni++) {
                if (vA) { float2 v; v.x = d[mi][ni][0]; v.y = d[mi][ni][1];
                          *(float2*)(cA + ni * 8) = v; }
                if (vB) { float2 v; v.x = d[mi][ni][2]; v.y = d[mi][ni][3];
                          *(float2*)(cB + ni * 8) = v; }
            }
        }
    }
}

// ---------------- combine ----------------
__global__ void combine_kernel(float* __restrict__ out, int total4) {
    int i = blockIdx.x * blockDim.x + threadIdx.x;
    if (i >= total4) return;
    int c = i % (D_HID/4);
    int t = i / (D_HID/4);
    float w0 = g_wt[2*t], w1 = g_wt[2*t+1];
    int s0 = g_p2s[2*t], s1 = g_p2s[2*t+1];
    float4 c0 = ((const float4*)(g_ct + (size_t)s0 * D_HID))[c];
    float4 c1 = ((const float4*)(g_ct + (size_t)s1 * D_HID))[c];
    float4 o;
    o.x = fmaf(w0, c0.x, w1 * c1.x);
    o.y = fmaf(w0, c0.y, w1 * c1.y);
    o.z = fmaf(w0, c0.z, w1 * c1.z);
    o.w = fmaf(w0, c0.w, w1 * c1.w);
    ((float4*)out)[i] = o;
}

// ---------------- launch ----------------
extern "C" void kernel_launch(void* const* d_in, const int* in_sizes, int n_in,
                              void* d_out, int out_size) {
    const float* x   = (const float*)d_in[0];
    const float* rw  = (const float*)d_in[1];
    const float* gup = (const float*)d_in[2];
    const float* dwn = (const float*)d_in[3];
    float* out = (float*)d_out;
    int T = in_sizes[0] / D_HID;

    cudaFuncSetAttribute(moe_gemm_kernel<0>, cudaFuncAttributeMaxDynamicSharedMemorySize, GEMM_SMEM);
    cudaFuncSetAttribute(moe_gemm_kernel<1>, cudaFuncAttributeMaxDynamicSharedMemorySize, GEMM_SMEM);

    zero_counts_kernel<<<1, 32>>>();                       // 0
    router_kernel<<<T, 256>>>(x, rw);                      // 1
    int prep_blocks = TPAIR + NEXP * NGU + NEXP * D_HID;
    prep_kernel<<<prep_blocks, 128>>>(x, gup, dwn);        // 2

    dim3 g0(32, NGU / 128, NEXP);                          // 3 (GEMM1 @ index 3)
    moe_gemm_kernel<0><<<g0, 256, GEMM_SMEM>>>();

    dim3 g1(32, D_HID / 128, NEXP);                        // 4
    moe_gemm_kernel<1><<<g1, 256, GEMM_SMEM>>>();

    combine_kernel<<<(T * (D_HID/4) + 255) / 256, 256>>>(out, T * (D_HID/4)); // 5
}

// round 8
// speedup vs baseline: 1.6723x; 1.1301x over previous
#include <cuda_runtime.h>
#include <cuda_fp16.h>
#include <cstdint>
#include <math.h>

#define D_HID 2048
#define INTER 1408
#define NGU   2816
#define NEXP  8
#define TMAX  4096
#define TPAIR 8192
#define RMAX  9216

// ---------------- device scratch ----------------
__device__ int   g_count[NEXP];
__device__ int   g_top_e[TPAIR];
__device__ int   g_pos[TPAIR];
__device__ int   g_p2s[TPAIR];
__device__ float g_wt[TPAIR];
__device__ __align__(256) __half g_xg_hi [(size_t)RMAX * D_HID];
__device__ __align__(256) __half g_xg_lo [(size_t)RMAX * D_HID];
__device__ __align__(256) __half g_gup   [(size_t)NEXP * NGU * D_HID];
__device__ __align__(256) __half g_dwn   [(size_t)NEXP * D_HID * INTER];
__device__ __align__(256) __half g_h     [(size_t)RMAX * INTER];
__device__ __align__(256) float  g_ct    [(size_t)RMAX * D_HID];

// ---------------- helpers ----------------
__device__ __forceinline__ uint32_t smem_u32(const void* p) {
    uint32_t a;
    asm("{ .reg .u64 t; cvta.to.shared.u64 t, %1; cvt.u32.u64 %0, t; }" : "=r"(a) : "l"(p));
    return a;
}
__device__ __forceinline__ void cp16z(uint32_t dst, const void* src, uint32_t sz) {
    asm volatile("cp.async.cg.shared.global [%0], [%1], 16, %2;"
                 :: "r"(dst), "l"(src), "r"(sz));
}
__device__ __forceinline__ void ldsm4(uint32_t* r, uint32_t addr) {
    asm volatile("ldmatrix.sync.aligned.m8n8.x4.shared.b16 {%0,%1,%2,%3}, [%4];"
                 : "=r"(r[0]), "=r"(r[1]), "=r"(r[2]), "=r"(r[3]) : "r"(addr));
}
__device__ __forceinline__ void mma_f16(float* d, const uint32_t* a, const uint32_t* b) {
    asm volatile("mma.sync.aligned.m16n8k16.row.col.f32.f16.f16.f32 "
                 "{%0,%1,%2,%3}, {%4,%5,%6,%7}, {%8,%9}, {%0,%1,%2,%3};"
                 : "+f"(d[0]), "+f"(d[1]), "+f"(d[2]), "+f"(d[3])
                 : "r"(a[0]), "r"(a[1]), "r"(a[2]), "r"(a[3]), "r"(b[0]), "r"(b[1]));
}
__device__ __forceinline__ void f2h2(float x, __half& hi, __half& lo) {
    hi = __float2half(x);
    lo = __float2half(x - __half2float(hi));
}
__device__ __forceinline__ int expert_base(int e) {
    int o = 0;
#pragma unroll
    for (int k = 0; k < NEXP; k++)
        if (k < e) o += (g_count[k] + 127) & ~127;
    return o;
}

// ---------------- init ----------------
__global__ void zero_counts_kernel() {
    if (threadIdx.x < NEXP) g_count[threadIdx.x] = 0;
}

// ---------------- router ----------------
__global__ void router_kernel(const float* __restrict__ x,
                              const float* __restrict__ rw) {
    int t = blockIdx.x;
    const float* xr = x + (size_t)t * D_HID;
    float p[NEXP];
#pragma unroll
    for (int e = 0; e < NEXP; e++) p[e] = 0.f;
    for (int d = threadIdx.x; d < D_HID; d += blockDim.x) {
        float xv = xr[d];
#pragma unroll
        for (int e = 0; e < NEXP; e++)
            p[e] = fmaf(xv, rw[e * D_HID + d], p[e]);
    }
#pragma unroll
    for (int off = 16; off > 0; off >>= 1)
#pragma unroll
        for (int e = 0; e < NEXP; e++)
            p[e] += __shfl_down_sync(0xffffffffu, p[e], off);
    __shared__ float s[8][NEXP];
    int warp = threadIdx.x >> 5;
    if ((threadIdx.x & 31) == 0)
#pragma unroll
        for (int e = 0; e < NEXP; e++) s[warp][e] = p[e];
    __syncthreads();
    if (threadIdx.x == 0) {
        float l[NEXP];
#pragma unroll
        for (int e = 0; e < NEXP; e++) {
            float a = 0.f;
#pragma unroll
            for (int w = 0; w < 8; w++) a += s[w][e];
            l[e] = a;
        }
        int i0 = 0;
#pragma unroll
        for (int e = 1; e < NEXP; e++) if (l[e] > l[i0]) i0 = e;
        int i1 = (i0 == 0) ? 1 : 0;
#pragma unroll
        for (int e = 0; e < NEXP; e++)
            if (e != i0 && l[e] > l[i1]) i1 = e;
        float e1  = expf(l[i1] - l[i0]);
        float inv = 1.f / (1.f + e1);
        g_wt[2*t]   = inv;
        g_wt[2*t+1] = e1 * inv;
        int p0 = atomicAdd(&g_count[i0], 1);
        g_top_e[2*t] = i0; g_pos[2*t] = p0;
        int p1 = atomicAdd(&g_count[i1], 1);
        g_top_e[2*t+1] = i1; g_pos[2*t+1] = p1;
    }
}

// ---------------- prep: gather-x (fp16 hi/lo) + weight fp16 conversions -----
__global__ void prep_kernel(const float* __restrict__ x,
                            const float* __restrict__ gup,
                            const float* __restrict__ dwn) {
    int b = blockIdx.x;
    if (b < TPAIR) {
        int p = b;
        int t = p >> 1;
        int s = expert_base(g_top_e[p]) + g_pos[p];
        if (threadIdx.x == 0) g_p2s[p] = s;
        const float4* src = (const float4*)(x + (size_t)t * D_HID);
        __half2* dh = (__half2*)(g_xg_hi + (size_t)s * D_HID);
        __half2* dl = (__half2*)(g_xg_lo + (size_t)s * D_HID);
        for (int i = threadIdx.x; i < D_HID/4; i += blockDim.x) {
            float4 v = src[i];
            __half h0,l0,h1,l1,h2,l2,h3,l3;
            f2h2(v.x,h0,l0); f2h2(v.y,h1,l1); f2h2(v.z,h2,l2); f2h2(v.w,h3,l3);
            dh[2*i]   = __halves2half2(h0, h1);
            dh[2*i+1] = __halves2half2(h2, h3);
            dl[2*i]   = __halves2half2(l0, l1);
            dl[2*i+1] = __halves2half2(l2, l3);
        }
    } else if (b < TPAIR + NEXP * NGU) {
        int row = b - TPAIR;
        int e = row / NGU;
        int n = row % NGU;
        int blk = n >> 6, r = n & 63;
        int src_n = (r < 32) ? (blk*32 + r) : (INTER + blk*32 + (r - 32));
        const float4* src = (const float4*)(gup + ((size_t)e * NGU + src_n) * D_HID);
        __half2* dh = (__half2*)(g_gup + (size_t)row * D_HID);
        for (int i = threadIdx.x; i < D_HID/4; i += blockDim.x) {
            float4 v = src[i];
            dh[2*i]   = __halves2half2(__float2half(v.x), __float2half(v.y));
            dh[2*i+1] = __halves2half2(__float2half(v.z), __float2half(v.w));
        }
    } else {
        int row = b - TPAIR - NEXP * NGU;
        const float4* src = (const float4*)(dwn + (size_t)row * INTER);
        __half2* dh = (__half2*)(g_dwn + (size_t)row * INTER);
        for (int i = threadIdx.x; i < INTER/4; i += blockDim.x) {
            float4 v = src[i];
            dh[2*i]   = __halves2half2(__float2half(v.x), __float2half(v.y));
            dh[2*i+1] = __halves2half2(__float2half(v.z), __float2half(v.w));
        }
    }
}

// ---------------- HMMA grouped GEMM ---------------------
// CTA tile 128x128, 256 threads (8 warps: 4 in M x 2 in N), 2 CTAs/SM
// PHASE 0: A split-2 (xg hi/lo), fused SwiGLU epilogue -> g_h (fp16)
// PHASE 1: A single (g_h), fp32 epilogue -> g_ct
#define PITCH 80
#define A_TILE (128*PITCH)           // 10240

template <int PHASE>
__global__ void __launch_bounds__(256, 2)
moe_gemm_kernel() {
    constexpr int Kd  = (PHASE == 0) ? D_HID : INTER;   // 2048 / 1408
    constexpr int NCH = Kd / 32;                        // 64 / 44
    constexpr int NROW = (PHASE == 0) ? NGU : D_HID;
    constexpr bool SPLIT = (PHASE == 0);
    constexpr int AL_OFF = A_TILE;                      // valid only if SPLIT
    constexpr int B_OFF  = SPLIT ? 2*A_TILE : A_TILE;
    constexpr int STAGE  = SPLIT ? 3*A_TILE : 2*A_TILE; // 30720 / 20480
    constexpr int NSTG   = 3;

    int e   = blockIdx.z;
    int cnt = g_count[e];
    int m0  = blockIdx.x * 128;
    if (m0 >= cnt) return;
    int n0  = blockIdx.y * 128;
    int off_e = expert_base(e);

    const __half* Ahi = ((PHASE == 0) ? g_xg_hi : g_h) + (size_t)(off_e + m0) * Kd;
    const __half* Alo = g_xg_lo + (size_t)(off_e + m0) * Kd;   // used only if SPLIT
    const __half* B   = ((PHASE == 0) ? g_gup : g_dwn) + ((size_t)e * NROW + n0) * Kd;

    extern __shared__ __align__(128) char smem[];
    uint32_t sb = smem_u32(smem);

    int tid = threadIdx.x;
    int wid = tid >> 5;
    int lid = tid & 31;
    int warp_m = (wid >> 1) * 32;
    int warp_n = (wid & 1) * 64;

    int r0 = tid >> 2, qa = tid & 3;
    int r1 = r0 + 64;
    uint32_t so0 = (uint32_t)(r0 * PITCH + qa * 16);
    uint32_t so1 = (uint32_t)(r1 * PITCH + qa * 16);
    const char* pAh0 = (const char*)(Ahi + (size_t)r0 * Kd + qa * 8);
    const char* pAh1 = (const char*)(Ahi + (size_t)r1 * Kd + qa * 8);
    const char* pAl0 = (const char*)(Alo + (size_t)r0 * Kd + qa * 8);
    const char* pAl1 = (const char*)(Alo + (size_t)r1 * Kd + qa * 8);
    const char* pB0  = (const char*)(B   + (size_t)r0 * Kd + qa * 8);
    const char* pB1  = (const char*)(B   + (size_t)r1 * Kd + qa * 8);
    uint32_t szA0 = (m0 + r0 < cnt) ? 16u : 0u;
    uint32_t szA1 = (m0 + r1 < cnt) ? 16u : 0u;

    uint32_t a_off = (uint32_t)((warp_m + (lid & 15)) * PITCH + (lid >> 4) * 16);
    uint32_t b_off = (uint32_t)((warp_n + (lid & 7) + ((lid & 16) >> 1)) * PITCH +
                                ((lid >> 3) & 1) * 16);

    float d[2][8][4];
#pragma unroll
    for (int mi = 0; mi < 2; mi++)
#pragma unroll
        for (int ni = 0; ni < 8; ni++)
#pragma unroll
            for (int k = 0; k < 4; k++) d[mi][ni][k] = 0.f;

    auto load_chunk = [&](int ci, int s) {
        uint32_t st = sb + s * STAGE;
        size_t go = (size_t)ci * 64;
        cp16z(st + so0, pAh0 + go, szA0);
        cp16z(st + so1, pAh1 + go, szA1);
        if (SPLIT) {
            cp16z(st + AL_OFF + so0, pAl0 + go, szA0);
            cp16z(st + AL_OFF + so1, pAl1 + go, szA1);
        }
        cp16z(st + B_OFF + so0, pB0 + go, 16u);
        cp16z(st + B_OFF + so1, pB1 + go, 16u);
    };

    load_chunk(0, 0);
    asm volatile("cp.async.commit_group;" ::: "memory");
    load_chunk(1, 1);
    asm volatile("cp.async.commit_group;" ::: "memory");

    int sidx = 0, lidx = 2;
#pragma unroll 1
    for (int i = 0; i < NCH; i++) {
        asm volatile("cp.async.wait_group 1;" ::: "memory");
        __syncthreads();
        if (i + 2 < NCH) load_chunk(i + 2, lidx);
        asm volatile("cp.async.commit_group;" ::: "memory");

        uint32_t st = sb + sidx * STAGE;
#pragma unroll
        for (int kk = 0; kk < 2; kk++) {
            uint32_t ko = kk * 32;
            uint32_t ah[2][4], al[2][4];
            ldsm4(ah[0], st + a_off + ko);
            ldsm4(ah[1], st + a_off + ko + 16 * PITCH);
            if (SPLIT) {
                ldsm4(al[0], st + AL_OFF + a_off + ko);
                ldsm4(al[1], st + AL_OFF + a_off + ko + 16 * PITCH);
            }
#pragma unroll
            for (int pp = 0; pp < 2; pp++) {
                uint32_t bf[2][4];
                ldsm4(bf[0], st + B_OFF + b_off + ko + (pp*2 + 0) * 16 * PITCH);
                ldsm4(bf[1], st + B_OFF + b_off + ko + (pp*2 + 1) * 16 * PITCH);
#pragma unroll
                for (int mi = 0; mi < 2; mi++)
#pragma unroll
                    for (int q = 0; q < 4; q++)
                        mma_f16(d[mi][pp*4 + q], ah[mi], &bf[q >> 1][(q & 1) * 2]);
                if (SPLIT) {
#pragma unroll
                    for (int mi = 0; mi < 2; mi++)
#pragma unroll
                        for (int q = 0; q < 4; q++)
                            mma_f16(d[mi][pp*4 + q], al[mi], &bf[q >> 1][(q & 1) * 2]);
                }
            }
        }
        sidx = (sidx == NSTG-1) ? 0 : sidx + 1;
        lidx = (lidx == NSTG-1) ? 0 : lidx + 1;
    }

    // ---------------- epilogue ----------------
    if (PHASE == 0) {
        int icb = blockIdx.y * 64 + (warp_n >> 1);
#pragma unroll
        for (int mi = 0; mi < 2; mi++) {
            int rA = warp_m + mi * 16 + (lid >> 2);
            int rB = rA + 8;
            bool vA = (m0 + rA) < cnt;
            bool vB = (m0 + rB) < cnt;
            size_t rowA = (size_t)(off_e + m0 + rA);
            size_t rowB = (size_t)(off_e + m0 + rB);
#pragma unroll
            for (int ni = 0; ni < 4; ni++) {
                int col = icb + ni * 8 + (lid & 3) * 2;
                const float* g = d[mi][ni];
                const float* u = d[mi][ni + 4];
                if (vA) {
                    float h0 = g[0] / (1.f + expf(-g[0])) * u[0];
                    float h1 = g[1] / (1.f + expf(-g[1])) * u[1];
                    *(__half2*)(g_h + rowA * INTER + col) =
                        __halves2half2(__float2half(h0), __float2half(h1));
                }
                if (vB) {
                    float h0 = g[2] / (1.f + expf(-g[2])) * u[2];
                    float h1 = g[3] / (1.f + expf(-g[3])) * u[3];
                    *(__half2*)(g_h + rowB * INTER + col) =
                        __halves2half2(__float2half(h0), __float2half(h1));
                }
            }
        }
    } else {
#pragma unroll
        for (int mi = 0; mi < 2; mi++) {
            int rA = warp_m + mi * 16 + (lid >> 2);
            int rB = rA + 8;
            bool vA = (m0 + rA) < cnt;
            bool vB = (m0 + rB) < cnt;
            float* cA = g_ct + (size_t)(off_e + m0 + rA) * D_HID + n0 + warp_n + (lid & 3) * 2;
            float* cB = g_ct + (size_t)(off_e + m0 + rB) * D_HID + n0 + warp_n + (lid & 3) * 2;
#pragma unroll
            for (int ni = 0; ni < 8; ni++) {
                if (vA) { float2 v; v.x = d[mi][ni][0]; v.y = d[mi][ni][1];
                          *(float2*)(cA + ni * 8) = v; }
                if (vB) { float2 v; v.x = d[mi][ni][2]; v.y = d[mi][ni][3];
                          *(float2*)(cB + ni * 8) = v; }
            }
        }
    }
}

#define GEMM_SMEM0 (3*3*A_TILE)   // 92160
#define GEMM_SMEM1 (3*2*A_TILE)   // 61440

// ---------------- combine ----------------
__global__ void combine_kernel(float* __restrict__ out, int total4) {
    int i = blockIdx.x * blockDim.x + threadIdx.x;
    if (i >= total4) return;
    int c = i % (D_HID/4);
    int t = i / (D_HID/4);
    float w0 = g_wt[2*t], w1 = g_wt[2*t+1];
    int s0 = g_p2s[2*t], s1 = g_p2s[2*t+1];
    float4 c0 = ((const float4*)(g_ct + (size_t)s0 * D_HID))[c];
    float4 c1 = ((const float4*)(g_ct + (size_t)s1 * D_HID))[c];
    float4 o;
    o.x = fmaf(w0, c0.x, w1 * c1.x);
    o.y = fmaf(w0, c0.y, w1 * c1.y);
    o.z = fmaf(w0, c0.z, w1 * c1.z);
    o.w = fmaf(w0, c0.w, w1 * c1.w);
    ((float4*)out)[i] = o;
}

// ---------------- launch ----------------
extern "C" void kernel_launch(void* const* d_in, const int* in_sizes, int n_in,
                              void* d_out, int out_size) {
    const float* x   = (const float*)d_in[0];
    const float* rw  = (const float*)d_in[1];
    const float* gup = (const float*)d_in[2];
    const float* dwn = (const float*)d_in[3];
    float* out = (float*)d_out;
    int T = in_sizes[0] / D_HID;

    cudaFuncSetAttribute(moe_gemm_kernel<0>, cudaFuncAttributeMaxDynamicSharedMemorySize, GEMM_SMEM0);
    cudaFuncSetAttribute(moe_gemm_kernel<1>, cudaFuncAttributeMaxDynamicSharedMemorySize, GEMM_SMEM1);

    zero_counts_kernel<<<1, 32>>>();                       // 0
    router_kernel<<<T, 256>>>(x, rw);                      // 1
    int prep_blocks = TPAIR + NEXP * NGU + NEXP * D_HID;
    prep_kernel<<<prep_blocks, 128>>>(x, gup, dwn);        // 2

    dim3 g0(32, NGU / 128, NEXP);                          // 3 (GEMM1 @ index 3)
    moe_gemm_kernel<0><<<g0, 256, GEMM_SMEM0>>>();

    dim3 g1(32, D_HID / 128, NEXP);                        // 4
    moe_gemm_kernel<1><<<g1, 256, GEMM_SMEM1>>>();

    combine_kernel<<<(T * (D_HID/4) + 255) / 256, 256>>>(out, T * (D_HID/4)); // 5
}

// round 9
// speedup vs baseline: 2.2361x; 1.3372x over previous
#include <cuda_runtime.h>
#include <cuda_fp16.h>
#include <cstdint>
#include <math.h>

#define D_HID 2048
#define INTER 1408
#define NGU   2816
#define NEXP  8
#define TMAX  4096
#define TPAIR 8192
#define RMAX  9216

// ---------------- device scratch ----------------
__device__ int   g_count[NEXP];
__device__ int   g_top_e[TPAIR];
__device__ int   g_pos[TPAIR];
__device__ int   g_p2s[TPAIR];
__device__ float g_wt[TPAIR];
__device__ __align__(256) __half g_xg  [(size_t)RMAX * D_HID];
__device__ __align__(256) __half g_gup [(size_t)NEXP * NGU * D_HID];
__device__ __align__(256) __half g_dwn [(size_t)NEXP * D_HID * INTER];
__device__ __align__(256) __half g_h   [(size_t)RMAX * INTER];
__device__ __align__(256) float  g_ct  [(size_t)RMAX * D_HID];

// ---------------- helpers ----------------
__device__ __forceinline__ uint32_t smem_u32(const void* p) {
    uint32_t a;
    asm("{ .reg .u64 t; cvta.to.shared.u64 t, %1; cvt.u32.u64 %0, t; }" : "=r"(a) : "l"(p));
    return a;
}
__device__ __forceinline__ void cp16z(uint32_t dst, const void* src, uint32_t sz) {
    asm volatile("cp.async.cg.shared.global [%0], [%1], 16, %2;"
                 :: "r"(dst), "l"(src), "r"(sz));
}
__device__ __forceinline__ void ldsm4(uint32_t* r, uint32_t addr) {
    asm volatile("ldmatrix.sync.aligned.m8n8.x4.shared.b16 {%0,%1,%2,%3}, [%4];"
                 : "=r"(r[0]), "=r"(r[1]), "=r"(r[2]), "=r"(r[3]) : "r"(addr));
}
__device__ __forceinline__ void mma_f16(float* d, const uint32_t* a, const uint32_t* b) {
    asm volatile("mma.sync.aligned.m16n8k16.row.col.f32.f16.f16.f32 "
                 "{%0,%1,%2,%3}, {%4,%5,%6,%7}, {%8,%9}, {%0,%1,%2,%3};"
                 : "+f"(d[0]), "+f"(d[1]), "+f"(d[2]), "+f"(d[3])
                 : "r"(a[0]), "r"(a[1]), "r"(a[2]), "r"(a[3]), "r"(b[0]), "r"(b[1]));
}
__device__ __forceinline__ int expert_base(int e) {
    int o = 0;
#pragma unroll
    for (int k = 0; k < NEXP; k++)
        if (k < e) o += (g_count[k] + 127) & ~127;
    return o;
}

// ---------------- init ----------------
__global__ void zero_counts_kernel() {
    if (threadIdx.x < NEXP) g_count[threadIdx.x] = 0;
}

// ---------------- router ----------------
__global__ void router_kernel(const float* __restrict__ x,
                              const float* __restrict__ rw) {
    int t = blockIdx.x;
    const float* xr = x + (size_t)t * D_HID;
    float p[NEXP];
#pragma unroll
    for (int e = 0; e < NEXP; e++) p[e] = 0.f;
    for (int d = threadIdx.x; d < D_HID; d += blockDim.x) {
        float xv = xr[d];
#pragma unroll
        for (int e = 0; e < NEXP; e++)
            p[e] = fmaf(xv, rw[e * D_HID + d], p[e]);
    }
#pragma unroll
    for (int off = 16; off > 0; off >>= 1)
#pragma unroll
        for (int e = 0; e < NEXP; e++)
            p[e] += __shfl_down_sync(0xffffffffu, p[e], off);
    __shared__ float s[8][NEXP];
    int warp = threadIdx.x >> 5;
    if ((threadIdx.x & 31) == 0)
#pragma unroll
        for (int e = 0; e < NEXP; e++) s[warp][e] = p[e];
    __syncthreads();
    if (threadIdx.x == 0) {
        float l[NEXP];
#pragma unroll
        for (int e = 0; e < NEXP; e++) {
            float a = 0.f;
#pragma unroll
            for (int w = 0; w < 8; w++) a += s[w][e];
            l[e] = a;
        }
        int i0 = 0;
#pragma unroll
        for (int e = 1; e < NEXP; e++) if (l[e] > l[i0]) i0 = e;
        int i1 = (i0 == 0) ? 1 : 0;
#pragma unroll
        for (int e = 0; e < NEXP; e++)
            if (e != i0 && l[e] > l[i1]) i1 = e;
        float e1  = expf(l[i1] - l[i0]);
        float inv = 1.f / (1.f + e1);
        g_wt[2*t]   = inv;
        g_wt[2*t+1] = e1 * inv;
        int p0 = atomicAdd(&g_count[i0], 1);
        g_top_e[2*t] = i0; g_pos[2*t] = p0;
        int p1 = atomicAdd(&g_count[i1], 1);
        g_top_e[2*t+1] = i1; g_pos[2*t+1] = p1;
    }
}

// ---------------- prep: gather-x (fp16) + weight fp16 conversions ----------
__global__ void prep_kernel(const float* __restrict__ x,
                            const float* __restrict__ gup,
                            const float* __restrict__ dwn) {
    int b = blockIdx.x;
    if (b < TPAIR) {
        int p = b;
        int t = p >> 1;
        int s = expert_base(g_top_e[p]) + g_pos[p];
        if (threadIdx.x == 0) g_p2s[p] = s;
        const float4* src = (const float4*)(x + (size_t)t * D_HID);
        __half2* dh = (__half2*)(g_xg + (size_t)s * D_HID);
        for (int i = threadIdx.x; i < D_HID/4; i += blockDim.x) {
            float4 v = src[i];
            dh[2*i]   = __halves2half2(__float2half(v.x), __float2half(v.y));
            dh[2*i+1] = __halves2half2(__float2half(v.z), __float2half(v.w));
        }
    } else if (b < TPAIR + NEXP * NGU) {
        int row = b - TPAIR;
        int e = row / NGU;
        int n = row % NGU;
        int blk = n >> 6, r = n & 63;
        int src_n = (r < 32) ? (blk*32 + r) : (INTER + blk*32 + (r - 32));
        const float4* src = (const float4*)(gup + ((size_t)e * NGU + src_n) * D_HID);
        __half2* dh = (__half2*)(g_gup + (size_t)row * D_HID);
        for (int i = threadIdx.x; i < D_HID/4; i += blockDim.x) {
            float4 v = src[i];
            dh[2*i]   = __halves2half2(__float2half(v.x), __float2half(v.y));
            dh[2*i+1] = __halves2half2(__float2half(v.z), __float2half(v.w));
        }
    } else {
        int row = b - TPAIR - NEXP * NGU;
        const float4* src = (const float4*)(dwn + (size_t)row * INTER);
        __half2* dh = (__half2*)(g_dwn + (size_t)row * INTER);
        for (int i = threadIdx.x; i < INTER/4; i += blockDim.x) {
            float4 v = src[i];
            dh[2*i]   = __halves2half2(__float2half(v.x), __float2half(v.y));
            dh[2*i+1] = __halves2half2(__float2half(v.z), __float2half(v.w));
        }
    }
}

// ---------------- HMMA grouped GEMM (pure fp16) ---------------------
// CTA tile 128x128, 256 threads (8 warps: 4 in M x 2 in N), 2 CTAs/SM
// PHASE 0: A = g_xg, fused SwiGLU epilogue -> g_h (fp16)
// PHASE 1: A = g_h,  fp32 epilogue -> g_ct
#define PITCH 80
#define A_TILE (128*PITCH)           // 10240
#define B_OFF  A_TILE
#define STAGE  (2*A_TILE)            // 20480
#define NSTG   3
#define GEMM_SMEM (NSTG*STAGE)       // 61440

template <int PHASE>
__global__ void __launch_bounds__(256, 2)
moe_gemm_kernel() {
    constexpr int Kd  = (PHASE == 0) ? D_HID : INTER;   // 2048 / 1408
    constexpr int NCH = Kd / 32;                        // 64 / 44
    constexpr int NROW = (PHASE == 0) ? NGU : D_HID;

    int e   = blockIdx.z;
    int cnt = g_count[e];
    int m0  = blockIdx.x * 128;
    if (m0 >= cnt) return;
    int n0  = blockIdx.y * 128;
    int off_e = expert_base(e);

    const __half* A = ((PHASE == 0) ? g_xg : g_h) + (size_t)(off_e + m0) * Kd;
    const __half* B = ((PHASE == 0) ? g_gup : g_dwn) + ((size_t)e * NROW + n0) * Kd;

    extern __shared__ __align__(128) char smem[];
    uint32_t sb = smem_u32(smem);

    int tid = threadIdx.x;
    int wid = tid >> 5;
    int lid = tid & 31;
    int warp_m = (wid >> 1) * 32;
    int warp_n = (wid & 1) * 64;

    int r0 = tid >> 2, qa = tid & 3;
    int r1 = r0 + 64;
    uint32_t so0 = (uint32_t)(r0 * PITCH + qa * 16);
    uint32_t so1 = (uint32_t)(r1 * PITCH + qa * 16);
    const char* pA0 = (const char*)(A + (size_t)r0 * Kd + qa * 8);
    const char* pA1 = (const char*)(A + (size_t)r1 * Kd + qa * 8);
    const char* pB0 = (const char*)(B + (size_t)r0 * Kd + qa * 8);
    const char* pB1 = (const char*)(B + (size_t)r1 * Kd + qa * 8);
    uint32_t szA0 = (m0 + r0 < cnt) ? 16u : 0u;
    uint32_t szA1 = (m0 + r1 < cnt) ? 16u : 0u;

    uint32_t a_off = (uint32_t)((warp_m + (lid & 15)) * PITCH + (lid >> 4) * 16);
    uint32_t b_off = (uint32_t)((warp_n + (lid & 7) + ((lid & 16) >> 1)) * PITCH +
                                ((lid >> 3) & 1) * 16);

    float d[2][8][4];
#pragma unroll
    for (int mi = 0; mi < 2; mi++)
#pragma unroll
        for (int ni = 0; ni < 8; ni++)
#pragma unroll
            for (int k = 0; k < 4; k++) d[mi][ni][k] = 0.f;

    auto load_chunk = [&](int ci, int s) {
        uint32_t st = sb + s * STAGE;
        size_t go = (size_t)ci * 64;
        cp16z(st + so0, pA0 + go, szA0);
        cp16z(st + so1, pA1 + go, szA1);
        cp16z(st + B_OFF + so0, pB0 + go, 16u);
        cp16z(st + B_OFF + so1, pB1 + go, 16u);
    };

    load_chunk(0, 0);
    asm volatile("cp.async.commit_group;" ::: "memory");
    load_chunk(1, 1);
    asm volatile("cp.async.commit_group;" ::: "memory");

    int sidx = 0, lidx = 2;
#pragma unroll 1
    for (int i = 0; i < NCH; i++) {
        asm volatile("cp.async.wait_group 1;" ::: "memory");
        __syncthreads();
        if (i + 2 < NCH) load_chunk(i + 2, lidx);
        asm volatile("cp.async.commit_group;" ::: "memory");

        uint32_t st = sb + sidx * STAGE;
#pragma unroll
        for (int kk = 0; kk < 2; kk++) {
            uint32_t ko = kk * 32;
            uint32_t af[2][4];
            ldsm4(af[0], st + a_off + ko);
            ldsm4(af[1], st + a_off + ko + 16 * PITCH);
#pragma unroll
            for (int pp = 0; pp < 2; pp++) {
                uint32_t bf[2][4];
                ldsm4(bf[0], st + B_OFF + b_off + ko + (pp*2 + 0) * 16 * PITCH);
                ldsm4(bf[1], st + B_OFF + b_off + ko + (pp*2 + 1) * 16 * PITCH);
#pragma unroll
                for (int mi = 0; mi < 2; mi++)
#pragma unroll
                    for (int q = 0; q < 4; q++)
                        mma_f16(d[mi][pp*4 + q], af[mi], &bf[q >> 1][(q & 1) * 2]);
            }
        }
        sidx = (sidx == NSTG-1) ? 0 : sidx + 1;
        lidx = (lidx == NSTG-1) ? 0 : lidx + 1;
    }

    // ---------------- epilogue ----------------
    if (PHASE == 0) {
        int icb = blockIdx.y * 64 + (warp_n >> 1);
#pragma unroll
        for (int mi = 0; mi < 2; mi++) {
            int rA = warp_m + mi * 16 + (lid >> 2);
            int rB = rA + 8;
            bool vA = (m0 + rA) < cnt;
            bool vB = (m0 + rB) < cnt;
            size_t rowA = (size_t)(off_e + m0 + rA);
            size_t rowB = (size_t)(off_e + m0 + rB);
#pragma unroll
            for (int ni = 0; ni < 4; ni++) {
                int col = icb + ni * 8 + (lid & 3) * 2;
                const float* g = d[mi][ni];
                const float* u = d[mi][ni + 4];
                if (vA) {
                    float h0 = g[0] / (1.f + expf(-g[0])) * u[0];
                    float h1 = g[1] / (1.f + expf(-g[1])) * u[1];
                    *(__half2*)(g_h + rowA * INTER + col) =
                        __halves2half2(__float2half(h0), __float2half(h1));
                }
                if (vB) {
                    float h0 = g[2] / (1.f + expf(-g[2])) * u[2];
                    float h1 = g[3] / (1.f + expf(-g[3])) * u[3];
                    *(__half2*)(g_h + rowB * INTER + col) =
                        __halves2half2(__float2half(h0), __float2half(h1));
                }
            }
        }
    } else {
#pragma unroll
        for (int mi = 0; mi < 2; mi++) {
            int rA = warp_m + mi * 16 + (lid >> 2);
            int rB = rA + 8;
            bool vA = (m0 + rA) < cnt;
            bool vB = (m0 + rB) < cnt;
            float* cA = g_ct + (size_t)(off_e + m0 + rA) * D_HID + n0 + warp_n + (lid & 3) * 2;
            float* cB = g_ct + (size_t)(off_e + m0 + rB) * D_HID + n0 + warp_n + (lid & 3) * 2;
#pragma unroll
            for (int ni = 0; ni < 8; ni++) {
                if (vA) { float2 v; v.x = d[mi][ni][0]; v.y = d[mi][ni][1];
                          *(float2*)(cA + ni * 8) = v; }
                if (vB) { float2 v; v.x = d[mi][ni][2]; v.y = d[mi][ni][3];
                          *(float2*)(cB + ni * 8) = v; }
            }
        }
    }
}

// ---------------- combine ----------------
__global__ void combine_kernel(float* __restrict__ out, int total4) {
    int i = blockIdx.x * blockDim.x + threadIdx.x;
    if (i >= total4) return;
    int c = i % (D_HID/4);
    int t = i / (D_HID/4);
    float w0 = g_wt[2*t], w1 = g_wt[2*t+1];
    int s0 = g_p2s[2*t], s1 = g_p2s[2*t+1];
    float4 c0 = ((const float4*)(g_ct + (size_t)s0 * D_HID))[c];
    float4 c1 = ((const float4*)(g_ct + (size_t)s1 * D_HID))[c];
    float4 o;
    o.x = fmaf(w0, c0.x, w1 * c1.x);
    o.y = fmaf(w0, c0.y, w1 * c1.y);
    o.z = fmaf(w0, c0.z, w1 * c1.z);
    o.w = fmaf(w0, c0.w, w1 * c1.w);
    ((float4*)out)[i] = o;
}

// ---------------- launch ----------------
extern "C" void kernel_launch(void* const* d_in, const int* in_sizes, int n_in,
                              void* d_out, int out_size) {
    const float* x   = (const float*)d_in[0];
    const float* rw  = (const float*)d_in[1];
    const float* gup = (const float*)d_in[2];
    const float* dwn = (const float*)d_in[3];
    float* out = (float*)d_out;
    int T = in_sizes[0] / D_HID;

    cudaFuncSetAttribute(moe_gemm_kernel<0>, cudaFuncAttributeMaxDynamicSharedMemorySize, GEMM_SMEM);
    cudaFuncSetAttribute(moe_gemm_kernel<1>, cudaFuncAttributeMaxDynamicSharedMemorySize, GEMM_SMEM);

    zero_counts_kernel<<<1, 32>>>();                       // 0
    router_kernel<<<T, 256>>>(x, rw);                      // 1
    int prep_blocks = TPAIR + NEXP * NGU + NEXP * D_HID;
    prep_kernel<<<prep_blocks, 128>>>(x, gup, dwn);        // 2

    dim3 g0(32, NGU / 128, NEXP);                          // 3 (GEMM1 @ index 3)
    moe_gemm_kernel<0><<<g0, 256, GEMM_SMEM>>>();

    dim3 g1(32, D_HID / 128, NEXP);                        // 4
    moe_gemm_kernel<1><<<g1, 256, GEMM_SMEM>>>();

    combine_kernel<<<(T * (D_HID/4) + 255) / 256, 256>>>(out, T * (D_HID/4)); // 5
}

// round 10
// speedup vs baseline: 2.2791x; 1.0192x over previous
#include <cuda_runtime.h>
#include <cuda_fp16.h>
#include <cstdint>
#include <math.h>

#define D_HID 2048
#define INTER 1408
#define NGU   2816
#define NEXP  8
#define TMAX  4096
#define TPAIR 8192
#define RMAX  9216

// ---------------- device scratch ----------------
__device__ int   g_count[NEXP];
__device__ int   g_top_e[TPAIR];
__device__ int   g_pos[TPAIR];
__device__ int   g_p2s[TPAIR];
__device__ float g_wt[TPAIR];
__device__ __align__(256) __half g_xg  [(size_t)RMAX * D_HID];
__device__ __align__(256) __half g_gup [(size_t)NEXP * NGU * D_HID];
__device__ __align__(256) __half g_dwn [(size_t)NEXP * D_HID * INTER];
__device__ __align__(256) __half g_h   [(size_t)RMAX * INTER];
__device__ __align__(256) float  g_ct  [(size_t)RMAX * D_HID];

// ---------------- helpers ----------------
__device__ __forceinline__ uint32_t smem_u32(const void* p) {
    uint32_t a;
    asm("{ .reg .u64 t; cvta.to.shared.u64 t, %1; cvt.u32.u64 %0, t; }" : "=r"(a) : "l"(p));
    return a;
}
__device__ __forceinline__ void cp16z(uint32_t dst, const void* src, uint32_t sz) {
    asm volatile("cp.async.cg.shared.global [%0], [%1], 16, %2;"
                 :: "r"(dst), "l"(src), "r"(sz));
}
__device__ __forceinline__ void ldsm4(uint32_t* r, uint32_t addr) {
    asm volatile("ldmatrix.sync.aligned.m8n8.x4.shared.b16 {%0,%1,%2,%3}, [%4];"
                 : "=r"(r[0]), "=r"(r[1]), "=r"(r[2]), "=r"(r[3]) : "r"(addr));
}
__device__ __forceinline__ void mma_f16(float* d, const uint32_t* a, const uint32_t* b) {
    asm volatile("mma.sync.aligned.m16n8k16.row.col.f32.f16.f16.f32 "
                 "{%0,%1,%2,%3}, {%4,%5,%6,%7}, {%8,%9}, {%0,%1,%2,%3};"
                 : "+f"(d[0]), "+f"(d[1]), "+f"(d[2]), "+f"(d[3])
                 : "r"(a[0]), "r"(a[1]), "r"(a[2]), "r"(a[3]), "r"(b[0]), "r"(b[1]));
}
__device__ __forceinline__ int expert_base(int e) {
    int o = 0;
#pragma unroll
    for (int k = 0; k < NEXP; k++)
        if (k < e) o += (g_count[k] + 127) & ~127;
    return o;
}

// ---------------- init ----------------
__global__ void zero_counts_kernel() {
    if (threadIdx.x < NEXP) g_count[threadIdx.x] = 0;
}

// ---------------- router ----------------
__global__ void router_kernel(const float* __restrict__ x,
                              const float* __restrict__ rw) {
    int t = blockIdx.x;
    const float* xr = x + (size_t)t * D_HID;
    float p[NEXP];
#pragma unroll
    for (int e = 0; e < NEXP; e++) p[e] = 0.f;
    for (int d = threadIdx.x; d < D_HID; d += blockDim.x) {
        float xv = xr[d];
#pragma unroll
        for (int e = 0; e < NEXP; e++)
            p[e] = fmaf(xv, rw[e * D_HID + d], p[e]);
    }
#pragma unroll
    for (int off = 16; off > 0; off >>= 1)
#pragma unroll
        for (int e = 0; e < NEXP; e++)
            p[e] += __shfl_down_sync(0xffffffffu, p[e], off);
    __shared__ float s[8][NEXP];
    int warp = threadIdx.x >> 5;
    if ((threadIdx.x & 31) == 0)
#pragma unroll
        for (int e = 0; e < NEXP; e++) s[warp][e] = p[e];
    __syncthreads();
    if (threadIdx.x == 0) {
        float l[NEXP];
#pragma unroll
        for (int e = 0; e < NEXP; e++) {
            float a = 0.f;
#pragma unroll
            for (int w = 0; w < 8; w++) a += s[w][e];
            l[e] = a;
        }
        int i0 = 0;
#pragma unroll
        for (int e = 1; e < NEXP; e++) if (l[e] > l[i0]) i0 = e;
        int i1 = (i0 == 0) ? 1 : 0;
#pragma unroll
        for (int e = 0; e < NEXP; e++)
            if (e != i0 && l[e] > l[i1]) i1 = e;
        float e1  = expf(l[i1] - l[i0]);
        float inv = 1.f / (1.f + e1);
        g_wt[2*t]   = inv;
        g_wt[2*t+1] = e1 * inv;
        int p0 = atomicAdd(&g_count[i0], 1);
        g_top_e[2*t] = i0; g_pos[2*t] = p0;
        int p1 = atomicAdd(&g_count[i1], 1);
        g_top_e[2*t+1] = i1; g_pos[2*t+1] = p1;
    }
}

// ---------------- prep: gather-x (fp16) + weight fp16 conversions ----------
__global__ void prep_kernel(const float* __restrict__ x,
                            const float* __restrict__ gup,
                            const float* __restrict__ dwn) {
    int b = blockIdx.x;
    if (b < TPAIR) {
        int p = b;
        int t = p >> 1;
        int s = expert_base(g_top_e[p]) + g_pos[p];
        if (threadIdx.x == 0) g_p2s[p] = s;
        const float4* src = (const float4*)(x + (size_t)t * D_HID);
        __half2* dh = (__half2*)(g_xg + (size_t)s * D_HID);
        for (int i = threadIdx.x; i < D_HID/4; i += blockDim.x) {
            float4 v = src[i];
            dh[2*i]   = __halves2half2(__float2half(v.x), __float2half(v.y));
            dh[2*i+1] = __halves2half2(__float2half(v.z), __float2half(v.w));
        }
    } else if (b < TPAIR + NEXP * NGU) {
        int row = b - TPAIR;
        int e = row / NGU;
        int n = row % NGU;
        int blk = n >> 6, r = n & 63;
        int src_n = (r < 32) ? (blk*32 + r) : (INTER + blk*32 + (r - 32));
        const float4* src = (const float4*)(gup + ((size_t)e * NGU + src_n) * D_HID);
        __half2* dh = (__half2*)(g_gup + (size_t)row * D_HID);
        for (int i = threadIdx.x; i < D_HID/4; i += blockDim.x) {
            float4 v = src[i];
            dh[2*i]   = __halves2half2(__float2half(v.x), __float2half(v.y));
            dh[2*i+1] = __halves2half2(__float2half(v.z), __float2half(v.w));
        }
    } else {
        int row = b - TPAIR - NEXP * NGU;
        const float4* src = (const float4*)(dwn + (size_t)row * INTER);
        __half2* dh = (__half2*)(g_dwn + (size_t)row * INTER);
        for (int i = threadIdx.x; i < INTER/4; i += blockDim.x) {
            float4 v = src[i];
            dh[2*i]   = __halves2half2(__float2half(v.x), __float2half(v.y));
            dh[2*i+1] = __halves2half2(__float2half(v.z), __float2half(v.w));
        }
    }
}

// ---------------- HMMA grouped GEMM (pure fp16, K-chunk 64) ----------------
// CTA tile 128x128, 256 threads (8 warps: 4 in M x 2 in N), 2 CTAs/SM
// Stage holds a K=64 chunk as two K=32 subtiles; 2-stage pipeline.
// PHASE 0: A = g_xg, fused SwiGLU epilogue -> g_h (fp16)
// PHASE 1: A = g_h,  fp32 epilogue -> g_ct
#define PITCH 80
#define A_TILE (128*PITCH)           // 10240 (one K=32 subtile, A or B)
#define STAGE  (4*A_TILE)            // 40960: [A0|A1|B0|B1]
#define NSTG   2
#define GEMM_SMEM (NSTG*STAGE)       // 81920

template <int PHASE>
__global__ void __launch_bounds__(256, 2)
moe_gemm_kernel() {
    constexpr int Kd  = (PHASE == 0) ? D_HID : INTER;   // 2048 / 1408
    constexpr int NCH = Kd / 64;                        // 32 / 22
    constexpr int NROW = (PHASE == 0) ? NGU : D_HID;

    int e   = blockIdx.z;
    int cnt = g_count[e];
    int m0  = blockIdx.x * 128;
    if (m0 >= cnt) return;
    int n0  = blockIdx.y * 128;
    int off_e = expert_base(e);

    const __half* A = ((PHASE == 0) ? g_xg : g_h) + (size_t)(off_e + m0) * Kd;
    const __half* B = ((PHASE == 0) ? g_gup : g_dwn) + ((size_t)e * NROW + n0) * Kd;

    extern __shared__ __align__(128) char smem[];
    uint32_t sb = smem_u32(smem);

    int tid = threadIdx.x;
    int wid = tid >> 5;
    int lid = tid & 31;
    int warp_m = (wid >> 1) * 32;
    int warp_n = (wid & 1) * 64;

    int r0 = tid >> 2, qa = tid & 3;
    int r1 = r0 + 64;
    uint32_t so0 = (uint32_t)(r0 * PITCH + qa * 16);
    uint32_t so1 = (uint32_t)(r1 * PITCH + qa * 16);
    const char* pA0 = (const char*)(A + (size_t)r0 * Kd + qa * 8);
    const char* pA1 = (const char*)(A + (size_t)r1 * Kd + qa * 8);
    const char* pB0 = (const char*)(B + (size_t)r0 * Kd + qa * 8);
    const char* pB1 = (const char*)(B + (size_t)r1 * Kd + qa * 8);
    uint32_t szA0 = (m0 + r0 < cnt) ? 16u : 0u;
    uint32_t szA1 = (m0 + r1 < cnt) ? 16u : 0u;

    uint32_t a_off = (uint32_t)((warp_m + (lid & 15)) * PITCH + (lid >> 4) * 16);
    uint32_t b_off = (uint32_t)((warp_n + (lid & 7) + ((lid & 16) >> 1)) * PITCH +
                                ((lid >> 3) & 1) * 16);

    float d[2][8][4];
#pragma unroll
    for (int mi = 0; mi < 2; mi++)
#pragma unroll
        for (int ni = 0; ni < 8; ni++)
#pragma unroll
            for (int k = 0; k < 4; k++) d[mi][ni][k] = 0.f;

    // chunk = 64 K elements = 128 bytes; two 64B subtiles at +0 and +64
    auto load_chunk = [&](int ci, int s) {
        uint32_t st = sb + s * STAGE;
        size_t go = (size_t)ci * 128;
        cp16z(st + so0,            pA0 + go,      szA0);
        cp16z(st + so1,            pA1 + go,      szA1);
        cp16z(st + A_TILE + so0,   pA0 + go + 64, szA0);
        cp16z(st + A_TILE + so1,   pA1 + go + 64, szA1);
        cp16z(st + 2*A_TILE + so0, pB0 + go,      16u);
        cp16z(st + 2*A_TILE + so1, pB1 + go,      16u);
        cp16z(st + 3*A_TILE + so0, pB0 + go + 64, 16u);
        cp16z(st + 3*A_TILE + so1, pB1 + go + 64, 16u);
    };

    load_chunk(0, 0);
    asm volatile("cp.async.commit_group;" ::: "memory");

#pragma unroll 1
    for (int i = 0; i < NCH; i++) {
        asm volatile("cp.async.wait_group 0;" ::: "memory");
        __syncthreads();
        // safe: all warps finished computing stage (i+1)&1 at iter i-1
        if (i + 1 < NCH) {
            load_chunk(i + 1, (i + 1) & 1);
            asm volatile("cp.async.commit_group;" ::: "memory");
        }
        uint32_t st = sb + (i & 1) * STAGE;
#pragma unroll
        for (int sl = 0; sl < 4; sl++) {           // 4 K=16 slices
            uint32_t ab = st + (sl >> 1) * A_TILE;
            uint32_t bb = st + (2 + (sl >> 1)) * A_TILE;
            uint32_t ko = (sl & 1) * 32;
            uint32_t af[2][4];
            ldsm4(af[0], ab + a_off + ko);
            ldsm4(af[1], ab + a_off + ko + 16 * PITCH);
#pragma unroll
            for (int pp = 0; pp < 2; pp++) {
                uint32_t bf[2][4];
                ldsm4(bf[0], bb + b_off + ko + (pp*2 + 0) * 16 * PITCH);
                ldsm4(bf[1], bb + b_off + ko + (pp*2 + 1) * 16 * PITCH);
#pragma unroll
                for (int mi = 0; mi < 2; mi++)
#pragma unroll
                    for (int q = 0; q < 4; q++)
                        mma_f16(d[mi][pp*4 + q], af[mi], &bf[q >> 1][(q & 1) * 2]);
            }
        }
    }

    // ---------------- epilogue ----------------
    if (PHASE == 0) {
        int icb = blockIdx.y * 64 + (warp_n >> 1);
#pragma unroll
        for (int mi = 0; mi < 2; mi++) {
            int rA = warp_m + mi * 16 + (lid >> 2);
            int rB = rA + 8;
            bool vA = (m0 + rA) < cnt;
            bool vB = (m0 + rB) < cnt;
            size_t rowA = (size_t)(off_e + m0 + rA);
            size_t rowB = (size_t)(off_e + m0 + rB);
#pragma unroll
            for (int ni = 0; ni < 4; ni++) {
                int col = icb + ni * 8 + (lid & 3) * 2;
                const float* g = d[mi][ni];
                const float* u = d[mi][ni + 4];
                if (vA) {
                    float h0 = g[0] / (1.f + expf(-g[0])) * u[0];
                    float h1 = g[1] / (1.f + expf(-g[1])) * u[1];
                    *(__half2*)(g_h + rowA * INTER + col) =
                        __halves2half2(__float2half(h0), __float2half(h1));
                }
                if (vB) {
                    float h0 = g[2] / (1.f + expf(-g[2])) * u[2];
                    float h1 = g[3] / (1.f + expf(-g[3])) * u[3];
                    *(__half2*)(g_h + rowB * INTER + col) =
                        __halves2half2(__float2half(h0), __float2half(h1));
                }
            }
        }
    } else {
#pragma unroll
        for (int mi = 0; mi < 2; mi++) {
            int rA = warp_m + mi * 16 + (lid >> 2);
            int rB = rA + 8;
            bool vA = (m0 + rA) < cnt;
            bool vB = (m0 + rB) < cnt;
            float* cA = g_ct + (size_t)(off_e + m0 + rA) * D_HID + n0 + warp_n + (lid & 3) * 2;
            float* cB = g_ct + (size_t)(off_e + m0 + rB) * D_HID + n0 + warp_n + (lid & 3) * 2;
#pragma unroll
            for (int ni = 0; ni < 8; ni++) {
                if (vA) { float2 v; v.x = d[mi][ni][0]; v.y = d[mi][ni][1];
                          *(float2*)(cA + ni * 8) = v; }
                if (vB) { float2 v; v.x = d[mi][ni][2]; v.y = d[mi][ni][3];
                          *(float2*)(cB + ni * 8) = v; }
            }
        }
    }
}

// ---------------- combine ----------------
__global__ void combine_kernel(float* __restrict__ out, int total4) {
    int i = blockIdx.x * blockDim.x + threadIdx.x;
    if (i >= total4) return;
    int c = i % (D_HID/4);
    int t = i / (D_HID/4);
    float w0 = g_wt[2*t], w1 = g_wt[2*t+1];
    int s0 = g_p2s[2*t], s1 = g_p2s[2*t+1];
    float4 c0 = ((const float4*)(g_ct + (size_t)s0 * D_HID))[c];
    float4 c1 = ((const float4*)(g_ct + (size_t)s1 * D_HID))[c];
    float4 o;
    o.x = fmaf(w0, c0.x, w1 * c1.x);
    o.y = fmaf(w0, c0.y, w1 * c1.y);
    o.z = fmaf(w0, c0.z, w1 * c1.z);
    o.w = fmaf(w0, c0.w, w1 * c1.w);
    ((float4*)out)[i] = o;
}

// ---------------- launch ----------------
extern "C" void kernel_launch(void* const* d_in, const int* in_sizes, int n_in,
                              void* d_out, int out_size) {
    const float* x   = (const float*)d_in[0];
    const float* rw  = (const float*)d_in[1];
    const float* gup = (const float*)d_in[2];
    const float* dwn = (const float*)d_in[3];
    float* out = (float*)d_out;
    int T = in_sizes[0] / D_HID;

    cudaFuncSetAttribute(moe_gemm_kernel<0>, cudaFuncAttributeMaxDynamicSharedMemorySize, GEMM_SMEM);
    cudaFuncSetAttribute(moe_gemm_kernel<1>, cudaFuncAttributeMaxDynamicSharedMemorySize, GEMM_SMEM);

    zero_counts_kernel<<<1, 32>>>();                       // 0
    router_kernel<<<T, 256>>>(x, rw);                      // 1
    int prep_blocks = TPAIR + NEXP * NGU + NEXP * D_HID;
    prep_kernel<<<prep_blocks, 128>>>(x, gup, dwn);        // 2

    dim3 g0(32, NGU / 128, NEXP);                          // 3 (GEMM1 @ index 3)
    moe_gemm_kernel<0><<<g0, 256, GEMM_SMEM>>>();

    dim3 g1(32, D_HID / 128, NEXP);                        // 4
    moe_gemm_kernel<1><<<g1, 256, GEMM_SMEM>>>();

    combine_kernel<<<(T * (D_HID/4) + 255) / 256, 256>>>(out, T * (D_HID/4)); // 5
}